// round 4
// baseline (speedup 1.0000x reference)
#include <cuda_runtime.h>
#include <cuda_fp16.h>
#include <cuda_bf16.h>

// Problem constants
#define DD   64      // input dim
#define HH   256     // hidden dim
#define BB   256     // batch
#define TT   512     // encoder timesteps
#define GG   1024    // 4*H
#define WOUT 96      // decoder steps

#define NBLK 128     // persistent encoder grid (must be <= SM count)

// ---------------- static scratch (no cudaMalloc allowed) ----------------
__device__ float  g_W0[GG * 320];          // [p][0:64]=Wih0, [64:320]=Whh0 (rows gate-permuted)
__device__ float  g_b0[GG];
__device__ float  g_W1[GG * 512];          // [p][0:256]=Wih1, [256:512]=Whh1
__device__ float  g_b1[GG];
__device__ float  g_Wd[GG * 768];          // [p][0:512]=Wih_d, [512:768]=Whh_d
__device__ float  g_bd[GG];
__device__ float  g_enc1[(size_t)BB * TT * HH];   // layer-0 outputs, fp32
__device__ __half g_enc [(size_t)BB * TT * HH];   // layer-1 outputs, fp16 (fits L2)
__device__ float  g_h0[2][BB * HH];
__device__ float  g_h1[2][BB * HH];
__device__ float  g_c1[BB * HH];
__device__ float  g_inp[BB * 512];         // decoder [p | ctx]

__device__ unsigned g_bar_cnt;
__device__ volatile unsigned g_bar_phase;

// ---------------- prep: gate-interleave weights, zero state, reset barrier ----
// permuted row p = 4k+q  <-  original row q*H + k   (i,f,g,o interleaved per h-index)
__global__ void prep_kernel(
    const float* __restrict__ Wih0, const float* __restrict__ Whh0,
    const float* __restrict__ bih0, const float* __restrict__ bhh0,
    const float* __restrict__ Wih1, const float* __restrict__ Whh1,
    const float* __restrict__ bih1, const float* __restrict__ bhh1,
    const float* __restrict__ Wihd, const float* __restrict__ Whhd,
    const float* __restrict__ bihd, const float* __restrict__ bhhd)
{
    int p = blockIdx.x;          // 0..1023
    int k = p >> 2, q = p & 3;
    int r = q * HH + k;
    int tid = threadIdx.x;       // 256 threads

    if (tid < 64) g_W0[p * 320 + tid] = Wih0[r * 64 + tid];
    g_W0[p * 320 +  64 + tid] = Whh0[r * 256 + tid];

    g_W1[p * 512 +       tid] = Wih1[r * 256 + tid];
    g_W1[p * 512 + 256 + tid] = Whh1[r * 256 + tid];

    g_Wd[p * 768 +       tid] = Wihd[r * 512 + tid];
    g_Wd[p * 768 + 256 + tid] = Wihd[r * 512 + 256 + tid];
    g_Wd[p * 768 + 512 + tid] = Whhd[r * 256 + tid];

    if (tid == 0) {
        g_b0[p] = bih0[r] + bhh0[r];
        g_b1[p] = bih1[r] + bhh1[r];
        g_bd[p] = bihd[r] + bhhd[r];
        if (p == 0) { g_bar_cnt = 0; g_bar_phase = 0; }
    }
    int idx = p * 256 + tid;     // covers 262144 >= 65536
    if (idx < BB * HH) {
        g_h0[0][idx] = 0.f; g_h0[1][idx] = 0.f;
        g_h1[0][idx] = 0.f; g_h1[1][idx] = 0.f;
        g_c1[idx] = 0.f;
    }
}

// ---------------- grid barrier (sense-reversing, fence flushes L1) ----------
__device__ __forceinline__ void gridbar(unsigned* phase)
{
    __syncthreads();
    if (threadIdx.x == 0) {
        unsigned p = *phase;
        __threadfence();                              // publish our writes
        if (atomicAdd(&g_bar_cnt, 1u) == (unsigned)gridDim.x - 1u) {
            atomicExch(&g_bar_cnt, 0u);
            __threadfence();
            g_bar_phase = p + 1u;
        } else {
            while (g_bar_phase == p) { __nanosleep(32); }
        }
        __threadfence();                              // CCTL.IVALL: drop stale L1
        *phase = p + 1u;
    }
    __syncthreads();
}

__device__ __forceinline__ float sigf(float x) { return 1.f / (1.f + expf(-x)); }

// K-split dot: lane holds K4 weights (quarter of K), As row segment for its kq.
template<int K4>
__device__ __forceinline__ float rowdot(const float4* __restrict__ ap,
                                        const float (&Wreg)[K4])
{
    float a0 = 0.f, a1 = 0.f, a2 = 0.f, a3 = 0.f;
    #pragma unroll
    for (int j4 = 0; j4 < K4 / 4; j4++) {
        float4 a = ap[j4];
        a0 = fmaf(Wreg[4 * j4 + 0], a.x, a0);
        a1 = fmaf(Wreg[4 * j4 + 1], a.y, a1);
        a2 = fmaf(Wreg[4 * j4 + 2], a.z, a2);
        a3 = fmaf(Wreg[4 * j4 + 3], a.w, a3);
    }
    return (a0 + a1) + (a2 + a3);
}

// ---------------- persistent encoder ----------------
// 128 blocks: [0..63] layer0, [64..127] layer1. Block = (row-tile 64) x (col-tile 64).
// Warp w owns cols 8w..8w+7 of its tile; lane l: col8 = l&7, kq = l>>3 (K split in 4).
// Shared As layout: row stride 4*(K4+4) floats, kq segment stride (K4+4) (bank stagger).
__global__ __launch_bounds__(256, 1)
void enc_persist_kernel(const float* __restrict__ x_in)
{
    extern __shared__ float As[];
    __shared__ float cs[64 * 16];      // c-state tile, lives here for whole scan

    const int blk   = blockIdx.x;
    const int layer = blk >> 6;
    const int sub   = blk & 63;
    const int rt    = sub & 3;          // row tile 0..3
    const int ct    = sub >> 2;         // col tile 0..15
    const int r0    = rt * 64;
    const int tid   = threadIdx.x;
    const int w     = tid >> 5;
    const int l     = tid & 31;
    const int c8    = l & 7;
    const int kq    = l >> 3;
    const int col   = ct * 64 + 8 * w + c8;
    const int hl    = 2 * w + (l >> 2); // valid for writer lanes (l==0 || l==4)
    const unsigned FULL = 0xffffffffu;

    for (int i = tid; i < 1024; i += 256) cs[i] = 0.f;

    unsigned phase = 0;

    if (layer == 0) {
        // ---- layer 0: K = 320 (x 64 | h 256), K4 = 80 ----
        float Wreg[80];
        {
            const float* Wp = g_W0 + (size_t)col * 320 + kq * 80;
            #pragma unroll
            for (int j = 0; j < 80; j++) Wreg[j] = Wp[j];
        }
        const float breg = g_b0[col];

        for (int e = 0; e < TT + 1; e++) {
            int t = e;
            if (t < TT) {
                const float* __restrict__ hprev = g_h0[t & 1];
                // load As: 64 rows x 80 float4
                for (int idx = tid; idx < 64 * 80; idx += 256) {
                    int r = idx / 80, k = (idx % 80) * 4;
                    int row = r0 + r;
                    float4 v;
                    if (k < 64) v = *(const float4*)&x_in[((size_t)row * TT + t) * DD + k];
                    else        v = *(const float4*)&hprev[row * HH + (k - 64)];
                    int q = k / 80, j = k % 80;
                    *(float4*)&As[r * 336 + q * 84 + j] = v;
                }
                __syncthreads();
                float* __restrict__ hnew = g_h0[(t + 1) & 1];
                for (int r = 0; r < 64; r++) {
                    const float4* ap = (const float4*)&As[r * 336 + kq * 84];
                    float acc = rowdot<80>(ap, Wreg);
                    acc += __shfl_xor_sync(FULL, acc, 8);
                    acc += __shfl_xor_sync(FULL, acc, 16);
                    acc += breg;
                    float gi = __shfl_sync(FULL, acc, (l & 4) + 0);
                    float gf = __shfl_sync(FULL, acc, (l & 4) + 1);
                    float gg = __shfl_sync(FULL, acc, (l & 4) + 2);
                    float go = __shfl_sync(FULL, acc, (l & 4) + 3);
                    if ((l & 3) == 0 && l < 8) {
                        int row = r0 + r;
                        float iv = sigf(gi), fv = sigf(gf);
                        float gv = tanhf(gg), ov = sigf(go);
                        float cn = fv * cs[r * 16 + hl] + iv * gv;
                        cs[r * 16 + hl] = cn;
                        float hv = ov * tanhf(cn);
                        int hidx = ct * 16 + hl;
                        hnew[row * HH + hidx] = hv;
                        g_enc1[((size_t)row * TT + t) * HH + hidx] = hv;
                    }
                }
            }
            gridbar(&phase);
        }
    } else {
        // ---- layer 1: K = 512 (enc1 256 | h 256), K4 = 128 ----
        float Wreg[128];
        {
            const float* Wp = g_W1 + (size_t)col * 512 + kq * 128;
            #pragma unroll
            for (int j = 0; j < 128; j++) Wreg[j] = Wp[j];
        }
        const float breg = g_b1[col];

        for (int e = 0; e < TT + 1; e++) {
            int tt = e - 1;
            if (tt >= 0) {
                const float* __restrict__ hprev = g_h1[tt & 1];
                // load As: 64 rows x 128 float4
                for (int idx = tid; idx < 64 * 128; idx += 256) {
                    int r = idx >> 7, k = (idx & 127) * 4;
                    int row = r0 + r;
                    float4 v;
                    if (k < 256) v = *(const float4*)&g_enc1[((size_t)row * TT + tt) * HH + k];
                    else         v = *(const float4*)&hprev[row * HH + (k - 256)];
                    int q = k >> 7, j = k & 127;
                    *(float4*)&As[r * 528 + q * 132 + j] = v;
                }
                __syncthreads();
                float* __restrict__ hnew = g_h1[(tt + 1) & 1];
                for (int r = 0; r < 64; r++) {
                    const float4* ap = (const float4*)&As[r * 528 + kq * 132];
                    float acc = rowdot<128>(ap, Wreg);
                    acc += __shfl_xor_sync(FULL, acc, 8);
                    acc += __shfl_xor_sync(FULL, acc, 16);
                    acc += breg;
                    float gi = __shfl_sync(FULL, acc, (l & 4) + 0);
                    float gf = __shfl_sync(FULL, acc, (l & 4) + 1);
                    float gg = __shfl_sync(FULL, acc, (l & 4) + 2);
                    float go = __shfl_sync(FULL, acc, (l & 4) + 3);
                    if ((l & 3) == 0 && l < 8) {
                        int row = r0 + r;
                        float iv = sigf(gi), fv = sigf(gf);
                        float gv = tanhf(gg), ov = sigf(go);
                        float cn = fv * cs[r * 16 + hl] + iv * gv;
                        cs[r * 16 + hl] = cn;
                        float hv = ov * tanhf(cn);
                        int hidx = ct * 16 + hl;
                        hnew[row * HH + hidx] = hv;
                        g_enc[((size_t)row * TT + tt) * HH + hidx] = __float2half(hv);
                        if (tt == TT - 1) g_c1[row * HH + hidx] = cn;
                    }
                }
            }
            gridbar(&phase);
        }
    }
}

// ---------------- fused GEMM + LSTM-cell step (decoder cell, unchanged) ------
__device__ __forceinline__ void lstm_gemm_tile(
    const float* __restrict__ A0, long long lda0, int K0,
    const float* __restrict__ A1, long long lda1, int K1,
    const float* __restrict__ W,  int ldw,
    const float* __restrict__ bias,
    float* __restrict__ c, float* __restrict__ h_out,
    int bx, int by)
{
    __shared__ float As2[16][34];
    __shared__ float Ws[16][68];
    const int tid = threadIdx.x;
    const int tx = tid & 15, ty = tid >> 4;
    const int row0 = by * 32, col0 = bx * 64;
    float acc[2][4] = {{0.f,0.f,0.f,0.f},{0.f,0.f,0.f,0.f}};
    const int Ktot = K0 + K1;

    for (int kt = 0; kt < Ktot; kt += 16) {
        const float* Aseg; long long ldA; int kl;
        if (kt < K0) { Aseg = A0; ldA = lda0; kl = kt; }
        else         { Aseg = A1; ldA = lda1; kl = kt - K0; }
        {
            int r = tid >> 4, kk = tid & 15;
            As2[kk][r] = Aseg[(long long)(row0 + r) * ldA + kl + kk];
            int i1 = tid + 256; r = i1 >> 4; kk = i1 & 15;
            As2[kk][r] = Aseg[(long long)(row0 + r) * ldA + kl + kk];
        }
        #pragma unroll
        for (int i = 0; i < 4; i++) {
            int idx = tid + i * 256;
            int cc = idx >> 4, kk = idx & 15;
            Ws[kk][cc] = W[(long long)(col0 + cc) * ldw + kt + kk];
        }
        __syncthreads();
        #pragma unroll
        for (int kk = 0; kk < 16; kk++) {
            float2 av = *reinterpret_cast<const float2*>(&As2[kk][ty * 2]);
            float4 wv = *reinterpret_cast<const float4*>(&Ws[kk][tx * 4]);
            acc[0][0] = fmaf(av.x, wv.x, acc[0][0]);
            acc[0][1] = fmaf(av.x, wv.y, acc[0][1]);
            acc[0][2] = fmaf(av.x, wv.z, acc[0][2]);
            acc[0][3] = fmaf(av.x, wv.w, acc[0][3]);
            acc[1][0] = fmaf(av.y, wv.x, acc[1][0]);
            acc[1][1] = fmaf(av.y, wv.y, acc[1][1]);
            acc[1][2] = fmaf(av.y, wv.z, acc[1][2]);
            acc[1][3] = fmaf(av.y, wv.w, acc[1][3]);
        }
        __syncthreads();
    }

    const int hidx = (col0 >> 2) + tx;
    float4 bv = *reinterpret_cast<const float4*>(&bias[col0 + tx * 4]);
    #pragma unroll
    for (int rr = 0; rr < 2; rr++) {
        int row = row0 + ty * 2 + rr;
        float iv = sigf(acc[rr][0] + bv.x);
        float fv = sigf(acc[rr][1] + bv.y);
        float gv = tanhf(acc[rr][2] + bv.z);
        float ov = sigf(acc[rr][3] + bv.w);
        int ci = row * HH + hidx;
        float cn = fv * c[ci] + iv * gv;
        c[ci] = cn;
        h_out[ci] = ov * tanhf(cn);
    }
}

// ---------------- decoder attention (single pass, online softmax) + p-proj ---
__global__ __launch_bounds__(256)
void dec_attn_kernel(const float* __restrict__ prev_y, long long ldy,
                     const float* __restrict__ Wp, const float* __restrict__ bp, int s)
{
    int b = blockIdx.x;
    const float* h = g_h1[s & 1] + b * HH;
    __shared__ float sh_h[HH];
    __shared__ float sh_py[DD];
    __shared__ float sh_m[8], sh_s[8];
    __shared__ float sh_part[8][HH];
    int tid = threadIdx.x, lane = tid & 31, w = tid >> 5;

    sh_h[tid] = h[tid];
    if (tid < DD) sh_py[tid] = prev_y[(long long)b * ldy + tid];
    __syncthreads();

    float m = -1e30f, ssum = 0.f;
    float accv[8];
    #pragma unroll
    for (int c2 = 0; c2 < 8; c2++) accv[c2] = 0.f;
    const __half* ebase = g_enc + (long long)b * TT * HH;

    for (int i = 0; i < 64; i++) {
        int t = w * 64 + i;
        const __half* e = ebase + (long long)t * HH;
        float v[8];
        float dot = 0.f;
        #pragma unroll
        for (int c2 = 0; c2 < 8; c2++) {
            v[c2] = __half2float(e[lane + 32 * c2]);
            dot = fmaf(v[c2], sh_h[lane + 32 * c2], dot);
        }
        #pragma unroll
        for (int o = 16; o > 0; o >>= 1) dot += __shfl_xor_sync(0xffffffffu, dot, o);
        float score = dot * 0.0625f;                 // / sqrt(256)
        float nm  = fmaxf(m, score);
        float esc = __expf(m - nm);
        float p   = __expf(score - nm);
        ssum = ssum * esc + p;
        #pragma unroll
        for (int c2 = 0; c2 < 8; c2++) accv[c2] = accv[c2] * esc + p * v[c2];
        m = nm;
    }
    if (lane == 0) { sh_m[w] = m; sh_s[w] = ssum; }
    #pragma unroll
    for (int c2 = 0; c2 < 8; c2++) sh_part[w][lane + 32 * c2] = accv[c2];
    __syncthreads();

    float M = sh_m[0];
    #pragma unroll
    for (int ww = 1; ww < 8; ww++) M = fmaxf(M, sh_m[ww]);
    float num = 0.f, den = 0.f;
    #pragma unroll
    for (int ww = 0; ww < 8; ww++) {
        float f = __expf(sh_m[ww] - M);
        den += f * sh_s[ww];
        num += f * sh_part[ww][tid];
    }
    g_inp[b * 512 + 256 + tid] = num / den;          // ctx

    float pv = bp[tid];
    #pragma unroll 8
    for (int d = 0; d < DD; d++) pv = fmaf(sh_py[d], Wp[tid * DD + d], pv);
    g_inp[b * 512 + tid] = pv;                       // prev_y @ Wp^T + bp
}

// ---------------- decoder LSTM cell ----------------
__global__ __launch_bounds__(256)
void dec_lstm_kernel(int s)
{
    lstm_gemm_tile(g_inp, 512, 512,
                   g_h1[s & 1], HH, HH,
                   g_Wd, 768, g_bd,
                   g_c1, g_h1[(s + 1) & 1],
                   blockIdx.x, blockIdx.y);
}

// ---------------- decoder output: y = [h_new | ctx] @ Wo^T + bo ----------------
__global__ __launch_bounds__(256)
void dec_y_kernel(float* __restrict__ out, const float* __restrict__ Wo,
                  const float* __restrict__ bo, int s)
{
    __shared__ float sA[16][512];
    int tid = threadIdx.x;
    int rb = blockIdx.x * 16;
    const float* hN = g_h1[(s + 1) & 1];
    for (int i = tid; i < 16 * 512; i += 256) {
        int r = i >> 9, k = i & 511;
        sA[r][k] = (k < 256) ? hN[(rb + r) * HH + k] : g_inp[(rb + r) * 512 + k];
    }
    __syncthreads();
    int j  = tid & 63;
    int r0 = (tid >> 6) * 4;
    float a0 = bo[j], a1 = a0, a2 = a0, a3 = a0;
    const float4* Wrow = reinterpret_cast<const float4*>(Wo + j * 512);
    for (int k4 = 0; k4 < 128; k4++) {
        float4 wv = Wrow[k4];
        int k = k4 * 4;
        a0 = fmaf(wv.x, sA[r0+0][k], a0); a0 = fmaf(wv.y, sA[r0+0][k+1], a0);
        a0 = fmaf(wv.z, sA[r0+0][k+2], a0); a0 = fmaf(wv.w, sA[r0+0][k+3], a0);
        a1 = fmaf(wv.x, sA[r0+1][k], a1); a1 = fmaf(wv.y, sA[r0+1][k+1], a1);
        a1 = fmaf(wv.z, sA[r0+1][k+2], a1); a1 = fmaf(wv.w, sA[r0+1][k+3], a1);
        a2 = fmaf(wv.x, sA[r0+2][k], a2); a2 = fmaf(wv.y, sA[r0+2][k+1], a2);
        a2 = fmaf(wv.z, sA[r0+2][k+2], a2); a2 = fmaf(wv.w, sA[r0+2][k+3], a2);
        a3 = fmaf(wv.x, sA[r0+3][k], a3); a3 = fmaf(wv.y, sA[r0+3][k+1], a3);
        a3 = fmaf(wv.z, sA[r0+3][k+2], a3); a3 = fmaf(wv.w, sA[r0+3][k+3], a3);
    }
    long long base = ((long long)(rb + r0) * WOUT + s) * DD + j;
    out[base]                        = a0;
    out[base + 1LL * WOUT * DD]      = a1;
    out[base + 2LL * WOUT * DD]      = a2;
    out[base + 3LL * WOUT * DD]      = a3;
}

// ---------------- launch ----------------
extern "C" void kernel_launch(void* const* d_in, const int* in_sizes, int n_in,
                              void* d_out, int out_size)
{
    const float* x_in = (const float*)d_in[0];
    int o = (n_in > 1 && in_sizes[1] == 1) ? 2 : 1;
    const float* Wih0 = (const float*)d_in[o + 0];
    const float* Whh0 = (const float*)d_in[o + 1];
    const float* bih0 = (const float*)d_in[o + 2];
    const float* bhh0 = (const float*)d_in[o + 3];
    const float* Wih1 = (const float*)d_in[o + 4];
    const float* Whh1 = (const float*)d_in[o + 5];
    const float* bih1 = (const float*)d_in[o + 6];
    const float* bhh1 = (const float*)d_in[o + 7];
    const float* Wihd = (const float*)d_in[o + 8];
    const float* Whhd = (const float*)d_in[o + 9];
    const float* bihd = (const float*)d_in[o + 10];
    const float* bhhd = (const float*)d_in[o + 11];
    const float* Wp   = (const float*)d_in[o + 12];
    const float* bp   = (const float*)d_in[o + 13];
    const float* Wo   = (const float*)d_in[o + 14];
    const float* bo   = (const float*)d_in[o + 15];
    float* out = (float*)d_out;

    const int smem_bytes = 64 * 528 * 4;   // 135168 B (layer-1 As tile)
    cudaFuncSetAttribute(enc_persist_kernel,
                         cudaFuncAttributeMaxDynamicSharedMemorySize, smem_bytes);

    prep_kernel<<<GG, 256>>>(Wih0, Whh0, bih0, bhh0,
                             Wih1, Whh1, bih1, bhh1,
                             Wihd, Whhd, bihd, bhhd);

    // persistent two-layer encoder scan: ONE launch
    enc_persist_kernel<<<NBLK, 256, smem_bytes>>>(x_in);

    // decoder: 96 steps
    for (int s = 0; s < WOUT; s++) {
        const float* py = (s == 0) ? (x_in + (long long)(TT - 1) * DD)
                                   : (out + (long long)(s - 1) * DD);
        long long ldy = (s == 0) ? (long long)TT * DD : (long long)WOUT * DD;
        dec_attn_kernel<<<BB, 256>>>(py, ldy, Wp, bp, s);
        dec_lstm_kernel<<<dim3(16, 8), 256>>>(s);
        dec_y_kernel<<<16, 256>>>(out, Wo, bo, s);
    }
}

// round 5
// speedup vs baseline: 1.3427x; 1.3427x over previous
#include <cuda_runtime.h>
#include <cuda_fp16.h>
#include <cuda_bf16.h>

// Problem constants
#define DD   64      // input dim
#define HH   256     // hidden dim
#define BB   256     // batch
#define TT   512     // encoder timesteps
#define GG   1024    // 4*H
#define WOUT 96      // decoder steps

// ---------------- static scratch (no cudaMalloc allowed) ----------------
__device__ float  g_W0[GG * 320];          // [p][0:64]=Wih0, [64:320]=Whh0 (rows gate-permuted)
__device__ float  g_b0[GG];
__device__ float  g_W1[GG * 512];          // [p][0:256]=Wih1, [256:512]=Whh1
__device__ float  g_b1[GG];
__device__ float  g_Wd[GG * 768];          // [p][0:512]=Wih_d, [512:768]=Whh_d
__device__ float  g_bd[GG];
__device__ float  g_enc1[(size_t)BB * TT * HH];   // layer-0 outputs, fp32
__device__ __half g_enc [(size_t)BB * TT * HH];   // layer-1 outputs, fp16 (fits L2)
__device__ float  g_h0[2][BB * HH];
__device__ float  g_c0[BB * HH];
__device__ float  g_h1[2][BB * HH];
__device__ float  g_c1[BB * HH];
__device__ float  g_inp[BB * 512];         // decoder [p | ctx]

// ---------------- prep: gate-interleave weights, zero state ----------------
// permuted row p = 4k+q  <-  original row q*H + k   (i,f,g,o interleaved per h-index)
__global__ void prep_kernel(
    const float* __restrict__ Wih0, const float* __restrict__ Whh0,
    const float* __restrict__ bih0, const float* __restrict__ bhh0,
    const float* __restrict__ Wih1, const float* __restrict__ Whh1,
    const float* __restrict__ bih1, const float* __restrict__ bhh1,
    const float* __restrict__ Wihd, const float* __restrict__ Whhd,
    const float* __restrict__ bihd, const float* __restrict__ bhhd)
{
    int p = blockIdx.x;          // 0..1023
    int k = p >> 2, q = p & 3;
    int r = q * HH + k;
    int tid = threadIdx.x;       // 256 threads

    if (tid < 64) g_W0[p * 320 + tid] = Wih0[r * 64 + tid];
    g_W0[p * 320 +  64 + tid] = Whh0[r * 256 + tid];

    g_W1[p * 512 +       tid] = Wih1[r * 256 + tid];
    g_W1[p * 512 + 256 + tid] = Whh1[r * 256 + tid];

    g_Wd[p * 768 +       tid] = Wihd[r * 512 + tid];
    g_Wd[p * 768 + 256 + tid] = Wihd[r * 512 + 256 + tid];
    g_Wd[p * 768 + 512 + tid] = Whhd[r * 256 + tid];

    if (tid == 0) {
        g_b0[p] = bih0[r] + bhh0[r];
        g_b1[p] = bih1[r] + bhh1[r];
        g_bd[p] = bihd[r] + bhhd[r];
    }
    int idx = p * 256 + tid;     // covers 262144 >= 65536
    if (idx < BB * HH) {
        g_h0[0][idx] = 0.f; g_h0[1][idx] = 0.f; g_c0[idx] = 0.f;
        g_h1[0][idx] = 0.f; g_h1[1][idx] = 0.f; g_c1[idx] = 0.f;
    }
}

__device__ __forceinline__ float sigf(float x) { return 1.f / (1.f + expf(-x)); }

// ---------------- fused GEMM + LSTM-cell step (64x64 tile, 256 thr, 4x4 reg) --
// gates(64x64) = [A0|A1](rows) @ W^T(cols) + bias ; epilogue = LSTM cell update.
// Columns gate-interleaved: cols 4k..4k+3 = (i,f,g,o) of h-index col0/4 + tx.
// Double-buffered smem, ONE sync per 16-K tile.
__device__ __forceinline__ void lstm_gemm_tile64(
    const float* __restrict__ A0, long long lda0, int K0,
    const float* __restrict__ A1, long long lda1, int K1,
    const float* __restrict__ W,  int ldw,
    const float* __restrict__ bias,
    float* __restrict__ c, float* __restrict__ h_out,
    float* __restrict__ seq_out, __half* __restrict__ seqh_out, long long seq_stride,
    int bx, int by)
{
    __shared__ float As[2][16][68];   // [buf][kk][row], rows float4-aligned (68=4*17)
    __shared__ float Ws[2][16][68];   // [buf][kk][col]
    const int tid = threadIdx.x;
    const int tx  = tid & 15, ty = tid >> 4;
    const int row0 = by * 64, col0 = bx * 64;
    const int lr = tid >> 2;          // 0..63 : load row (A) / col (W)
    const int ks = (tid & 3) * 4;     // 0,4,8,12
    const int ntiles = (K0 + K1) >> 4;

    float acc[4][4] = {{0.f,0.f,0.f,0.f},{0.f,0.f,0.f,0.f},
                       {0.f,0.f,0.f,0.f},{0.f,0.f,0.f,0.f}};

    float4 aReg, wReg;
    // prologue: tile 0 (kt=0 always in A0 segment since K0 >= 64)
    aReg = *reinterpret_cast<const float4*>(&A0[(long long)(row0 + lr) * lda0 + ks]);
    wReg = *reinterpret_cast<const float4*>(&W [(long long)(col0 + lr) * ldw  + ks]);
    As[0][ks+0][lr] = aReg.x; As[0][ks+1][lr] = aReg.y;
    As[0][ks+2][lr] = aReg.z; As[0][ks+3][lr] = aReg.w;
    Ws[0][ks+0][lr] = wReg.x; Ws[0][ks+1][lr] = wReg.y;
    Ws[0][ks+2][lr] = wReg.z; Ws[0][ks+3][lr] = wReg.w;
    __syncthreads();

    int p = 0;
    for (int it = 0; it < ntiles; it++) {
        const int ktn = (it + 1) << 4;
        const bool more = (it + 1 < ntiles);
        if (more) {
            const float* Aseg; long long ldA; int kl;
            if (ktn < K0) { Aseg = A0; ldA = lda0; kl = ktn; }
            else          { Aseg = A1; ldA = lda1; kl = ktn - K0; }
            aReg = *reinterpret_cast<const float4*>(&Aseg[(long long)(row0 + lr) * ldA + kl + ks]);
            wReg = *reinterpret_cast<const float4*>(&W  [(long long)(col0 + lr) * ldw + ktn + ks]);
        }
        #pragma unroll
        for (int kk = 0; kk < 16; kk++) {
            float4 av = *reinterpret_cast<const float4*>(&As[p][kk][ty * 4]);
            float4 wv = *reinterpret_cast<const float4*>(&Ws[p][kk][tx * 4]);
            acc[0][0] = fmaf(av.x, wv.x, acc[0][0]);
            acc[0][1] = fmaf(av.x, wv.y, acc[0][1]);
            acc[0][2] = fmaf(av.x, wv.z, acc[0][2]);
            acc[0][3] = fmaf(av.x, wv.w, acc[0][3]);
            acc[1][0] = fmaf(av.y, wv.x, acc[1][0]);
            acc[1][1] = fmaf(av.y, wv.y, acc[1][1]);
            acc[1][2] = fmaf(av.y, wv.z, acc[1][2]);
            acc[1][3] = fmaf(av.y, wv.w, acc[1][3]);
            acc[2][0] = fmaf(av.z, wv.x, acc[2][0]);
            acc[2][1] = fmaf(av.z, wv.y, acc[2][1]);
            acc[2][2] = fmaf(av.z, wv.z, acc[2][2]);
            acc[2][3] = fmaf(av.z, wv.w, acc[2][3]);
            acc[3][0] = fmaf(av.w, wv.x, acc[3][0]);
            acc[3][1] = fmaf(av.w, wv.y, acc[3][1]);
            acc[3][2] = fmaf(av.w, wv.z, acc[3][2]);
            acc[3][3] = fmaf(av.w, wv.w, acc[3][3]);
        }
        if (more) {
            const int q = p ^ 1;
            As[q][ks+0][lr] = aReg.x; As[q][ks+1][lr] = aReg.y;
            As[q][ks+2][lr] = aReg.z; As[q][ks+3][lr] = aReg.w;
            Ws[q][ks+0][lr] = wReg.x; Ws[q][ks+1][lr] = wReg.y;
            Ws[q][ks+2][lr] = wReg.z; Ws[q][ks+3][lr] = wReg.w;
            __syncthreads();
            p = q;
        }
    }

    // epilogue: thread owns 4 rows x one h-index (4 interleaved gate cols)
    const int hidx = (col0 >> 2) + tx;
    float4 bv = *reinterpret_cast<const float4*>(&bias[col0 + tx * 4]);
    #pragma unroll
    for (int rr = 0; rr < 4; rr++) {
        int row = row0 + ty * 4 + rr;
        float iv = sigf(acc[rr][0] + bv.x);
        float fv = sigf(acc[rr][1] + bv.y);
        float gv = tanhf(acc[rr][2] + bv.z);
        float ov = sigf(acc[rr][3] + bv.w);
        int ci = row * HH + hidx;
        float cn = fv * c[ci] + iv * gv;
        c[ci] = cn;
        float hv = ov * tanhf(cn);
        h_out[ci] = hv;
        if (seq_out)  seq_out [(long long)row * seq_stride + hidx] = hv;
        if (seqh_out) seqh_out[(long long)row * seq_stride + hidx] = __float2half(hv);
    }
}

// ---------------- encoder: pipelined layer0(step t) + layer1(step t-1) ------
__global__ __launch_bounds__(256)
void enc_step_kernel(const float* __restrict__ x_in, int t)
{
    if (blockIdx.z == 0) {
        if (t >= TT) return;
        lstm_gemm_tile64(x_in + (long long)t * DD, (long long)TT * DD, DD,
                         g_h0[t & 1], HH, HH,
                         g_W0, 320, g_b0,
                         g_c0, g_h0[(t + 1) & 1],
                         g_enc1 + (long long)t * HH, nullptr, (long long)TT * HH,
                         blockIdx.x, blockIdx.y);
    } else {
        if (t == 0) return;
        int tt = t - 1;
        lstm_gemm_tile64(g_enc1 + (long long)tt * HH, (long long)TT * HH, HH,
                         g_h1[tt & 1], HH, HH,
                         g_W1, 512, g_b1,
                         g_c1, g_h1[(tt + 1) & 1],
                         nullptr, g_enc + (long long)tt * HH, (long long)TT * HH,
                         blockIdx.x, blockIdx.y);
    }
}

// ---------------- decoder attention (single pass, online softmax) + p-proj ---
__global__ __launch_bounds__(256)
void dec_attn_kernel(const float* __restrict__ prev_y, long long ldy,
                     const float* __restrict__ Wp, const float* __restrict__ bp, int s)
{
    int b = blockIdx.x;
    const float* h = g_h1[s & 1] + b * HH;
    __shared__ float sh_h[HH];
    __shared__ float sh_py[DD];
    __shared__ float sh_m[8], sh_s[8];
    __shared__ float sh_part[8][HH];
    int tid = threadIdx.x, lane = tid & 31, w = tid >> 5;

    sh_h[tid] = h[tid];
    if (tid < DD) sh_py[tid] = prev_y[(long long)b * ldy + tid];
    __syncthreads();

    float m = -1e30f, ssum = 0.f;
    float accv[8];
    #pragma unroll
    for (int c2 = 0; c2 < 8; c2++) accv[c2] = 0.f;
    const __half* ebase = g_enc + (long long)b * TT * HH;

    for (int i = 0; i < 64; i++) {
        int t = w * 64 + i;
        const __half* e = ebase + (long long)t * HH;
        float v[8];
        float dot = 0.f;
        #pragma unroll
        for (int c2 = 0; c2 < 8; c2++) {
            v[c2] = __half2float(e[lane + 32 * c2]);
            dot = fmaf(v[c2], sh_h[lane + 32 * c2], dot);
        }
        #pragma unroll
        for (int o = 16; o > 0; o >>= 1) dot += __shfl_xor_sync(0xffffffffu, dot, o);
        float score = dot * 0.0625f;                 // / sqrt(256)
        float nm  = fmaxf(m, score);
        float esc = __expf(m - nm);
        float p   = __expf(score - nm);
        ssum = ssum * esc + p;
        #pragma unroll
        for (int c2 = 0; c2 < 8; c2++) accv[c2] = accv[c2] * esc + p * v[c2];
        m = nm;
    }
    if (lane == 0) { sh_m[w] = m; sh_s[w] = ssum; }
    #pragma unroll
    for (int c2 = 0; c2 < 8; c2++) sh_part[w][lane + 32 * c2] = accv[c2];
    __syncthreads();

    float M = sh_m[0];
    #pragma unroll
    for (int ww = 1; ww < 8; ww++) M = fmaxf(M, sh_m[ww]);
    float num = 0.f, den = 0.f;
    #pragma unroll
    for (int ww = 0; ww < 8; ww++) {
        float f = __expf(sh_m[ww] - M);
        den += f * sh_s[ww];
        num += f * sh_part[ww][tid];
    }
    g_inp[b * 512 + 256 + tid] = num / den;          // ctx

    float pv = bp[tid];
    #pragma unroll 8
    for (int d = 0; d < DD; d++) pv = fmaf(sh_py[d], Wp[tid * DD + d], pv);
    g_inp[b * 512 + tid] = pv;                       // prev_y @ Wp^T + bp
}

// ---------------- decoder LSTM cell ----------------
__global__ __launch_bounds__(256)
void dec_lstm_kernel(int s)
{
    lstm_gemm_tile64(g_inp, 512, 512,
                     g_h1[s & 1], HH, HH,
                     g_Wd, 768, g_bd,
                     g_c1, g_h1[(s + 1) & 1],
                     nullptr, nullptr, 0,
                     blockIdx.x, blockIdx.y);
}

// ---------------- decoder output: y = [h_new | ctx] @ Wo^T + bo ----------------
__global__ __launch_bounds__(256)
void dec_y_kernel(float* __restrict__ out, const float* __restrict__ Wo,
                  const float* __restrict__ bo, int s)
{
    __shared__ float sA[16][512];
    int tid = threadIdx.x;
    int rb = blockIdx.x * 16;
    const float* hN = g_h1[(s + 1) & 1];
    for (int i = tid; i < 16 * 512; i += 256) {
        int r = i >> 9, k = i & 511;
        sA[r][k] = (k < 256) ? hN[(rb + r) * HH + k] : g_inp[(rb + r) * 512 + k];
    }
    __syncthreads();
    int j  = tid & 63;
    int r0 = (tid >> 6) * 4;
    float a0 = bo[j], a1 = a0, a2 = a0, a3 = a0;
    const float4* Wrow = reinterpret_cast<const float4*>(Wo + j * 512);
    for (int k4 = 0; k4 < 128; k4++) {
        float4 wv = Wrow[k4];
        int k = k4 * 4;
        a0 = fmaf(wv.x, sA[r0+0][k], a0); a0 = fmaf(wv.y, sA[r0+0][k+1], a0);
        a0 = fmaf(wv.z, sA[r0+0][k+2], a0); a0 = fmaf(wv.w, sA[r0+0][k+3], a0);
        a1 = fmaf(wv.x, sA[r0+1][k], a1); a1 = fmaf(wv.y, sA[r0+1][k+1], a1);
        a1 = fmaf(wv.z, sA[r0+1][k+2], a1); a1 = fmaf(wv.w, sA[r0+1][k+3], a1);
        a2 = fmaf(wv.x, sA[r0+2][k], a2); a2 = fmaf(wv.y, sA[r0+2][k+1], a2);
        a2 = fmaf(wv.z, sA[r0+2][k+2], a2); a2 = fmaf(wv.w, sA[r0+2][k+3], a2);
        a3 = fmaf(wv.x, sA[r0+3][k], a3); a3 = fmaf(wv.y, sA[r0+3][k+1], a3);
        a3 = fmaf(wv.z, sA[r0+3][k+2], a3); a3 = fmaf(wv.w, sA[r0+3][k+3], a3);
    }
    long long base = ((long long)(rb + r0) * WOUT + s) * DD + j;
    out[base]                        = a0;
    out[base + 1LL * WOUT * DD]      = a1;
    out[base + 2LL * WOUT * DD]      = a2;
    out[base + 3LL * WOUT * DD]      = a3;
}

// ---------------- launch ----------------
extern "C" void kernel_launch(void* const* d_in, const int* in_sizes, int n_in,
                              void* d_out, int out_size)
{
    const float* x_in = (const float*)d_in[0];
    int o = (n_in > 1 && in_sizes[1] == 1) ? 2 : 1;
    const float* Wih0 = (const float*)d_in[o + 0];
    const float* Whh0 = (const float*)d_in[o + 1];
    const float* bih0 = (const float*)d_in[o + 2];
    const float* bhh0 = (const float*)d_in[o + 3];
    const float* Wih1 = (const float*)d_in[o + 4];
    const float* Whh1 = (const float*)d_in[o + 5];
    const float* bih1 = (const float*)d_in[o + 6];
    const float* bhh1 = (const float*)d_in[o + 7];
    const float* Wihd = (const float*)d_in[o + 8];
    const float* Whhd = (const float*)d_in[o + 9];
    const float* bihd = (const float*)d_in[o + 10];
    const float* bhhd = (const float*)d_in[o + 11];
    const float* Wp   = (const float*)d_in[o + 12];
    const float* bp   = (const float*)d_in[o + 13];
    const float* Wo   = (const float*)d_in[o + 14];
    const float* bo   = (const float*)d_in[o + 15];
    float* out = (float*)d_out;

    prep_kernel<<<GG, 256>>>(Wih0, Whh0, bih0, bhh0,
                             Wih1, Whh1, bih1, bhh1,
                             Wihd, Whhd, bihd, bhhd);

    // encoder: pipelined two-layer scan, 513 launches, 128 blocks each
    for (int t = 0; t <= TT; t++)
        enc_step_kernel<<<dim3(16, 4, 2), 256>>>(x_in, t);

    // decoder: 96 steps
    for (int s = 0; s < WOUT; s++) {
        const float* py = (s == 0) ? (x_in + (long long)(TT - 1) * DD)
                                   : (out + (long long)(s - 1) * DD);
        long long ldy = (s == 0) ? (long long)TT * DD : (long long)WOUT * DD;
        dec_attn_kernel<<<BB, 256>>>(py, ldy, Wp, bp, s);
        dec_lstm_kernel<<<dim3(16, 4), 256>>>(s);
        dec_y_kernel<<<16, 256>>>(out, Wo, bo, s);
    }
}

// round 10
// speedup vs baseline: 2.9354x; 2.1862x over previous
#include <cuda_runtime.h>
#include <cuda_fp16.h>
#include <cuda_bf16.h>
#include <cstdint>

// Problem constants
#define DD   64      // input dim
#define HH   256     // hidden dim
#define BB   256     // batch
#define TT   512     // encoder timesteps
#define GG   1024    // 4*H
#define WOUT 96      // decoder steps

// ---------------- static scratch (no cudaMalloc allowed) ----------------
__device__ __half g_hW0[GG * 320];          // fp16 gate-permuted [p][0:64]=Wih0,[64:320]=Whh0
__device__ float  g_b0[GG];
__device__ __half g_hW1[GG * 512];          // [p][0:256]=Wih1, [256:512]=Whh1
__device__ float  g_b1[GG];
__device__ __half g_hWd[GG * 768];          // [p][0:512]=Wih_d, [512:768]=Whh_d
__device__ float  g_bd[GG];
__device__ __half g_x   [(size_t)BB * TT * DD];   // x_in fp16
__device__ __half g_enc1[(size_t)BB * TT * HH];   // layer-0 outputs fp16
__device__ __half g_enc [(size_t)BB * TT * HH];   // layer-1 outputs fp16
__device__ __half g_h0[2][BB * HH];
__device__ float  g_c0[BB * HH];
__device__ __half g_h1[2][BB * HH];
__device__ float  g_c1[BB * HH];
__device__ __half g_inp[BB * 512];          // decoder [p | ctx] fp16

// ---------------- prep: gate-interleave + fp16 weights, zero state ----------
// permuted row p = 4k+q  <-  original row q*H + k
__global__ void prep_kernel(
    const float* __restrict__ Wih0, const float* __restrict__ Whh0,
    const float* __restrict__ bih0, const float* __restrict__ bhh0,
    const float* __restrict__ Wih1, const float* __restrict__ Whh1,
    const float* __restrict__ bih1, const float* __restrict__ bhh1,
    const float* __restrict__ Wihd, const float* __restrict__ Whhd,
    const float* __restrict__ bihd, const float* __restrict__ bhhd)
{
    int p = blockIdx.x;          // 0..1023
    int k = p >> 2, q = p & 3;
    int r = q * HH + k;
    int tid = threadIdx.x;       // 256 threads

    if (tid < 64) g_hW0[p * 320 + tid] = __float2half(Wih0[r * 64 + tid]);
    g_hW0[p * 320 +  64 + tid] = __float2half(Whh0[r * 256 + tid]);

    g_hW1[p * 512 +       tid] = __float2half(Wih1[r * 256 + tid]);
    g_hW1[p * 512 + 256 + tid] = __float2half(Whh1[r * 256 + tid]);

    g_hWd[p * 768 +       tid] = __float2half(Wihd[r * 512 + tid]);
    g_hWd[p * 768 + 256 + tid] = __float2half(Wihd[r * 512 + 256 + tid]);
    g_hWd[p * 768 + 512 + tid] = __float2half(Whhd[r * 256 + tid]);

    if (tid == 0) {
        g_b0[p] = bih0[r] + bhh0[r];
        g_b1[p] = bih1[r] + bhh1[r];
        g_bd[p] = bihd[r] + bhhd[r];
    }
    int idx = p * 256 + tid;     // covers 262144 >= 65536
    if (idx < BB * HH) {
        g_h0[0][idx] = __float2half(0.f); g_h0[1][idx] = __float2half(0.f);
        g_h1[0][idx] = __float2half(0.f); g_h1[1][idx] = __float2half(0.f);
        g_c0[idx] = 0.f; g_c1[idx] = 0.f;
    }
}

__global__ void xconv_kernel(const float* __restrict__ x)
{
    size_t i = (size_t)blockIdx.x * blockDim.x + threadIdx.x;
    if (i < (size_t)BB * TT * DD) g_x[i] = __float2half(x[i]);
}

__device__ __forceinline__ float sigf(float x) { return 1.f / (1.f + expf(-x)); }

// One HMMA atom: D(16x8) += A(16x16,row) * B(16x8,col), fp16 in, fp32 accum.
__device__ __forceinline__ void mma16816(float* cc,
                                         uint32_t a0, uint32_t a1, uint32_t a2, uint32_t a3,
                                         uint32_t b0, uint32_t b1)
{
    asm volatile(
        "mma.sync.aligned.m16n8k16.row.col.f32.f16.f16.f32 "
        "{%0,%1,%2,%3}, {%4,%5,%6,%7}, {%8,%9}, {%0,%1,%2,%3};"
        : "+f"(cc[0]), "+f"(cc[1]), "+f"(cc[2]), "+f"(cc[3])
        : "r"(a0), "r"(a1), "r"(a2), "r"(a3), "r"(b0), "r"(b1));
}

// ---------------- fused HMMA GEMM + LSTM-cell (64x64 tile, 8 warps) ----------
// gates(64x64) = [A0|A1] @ W^T + bias, fp16 operands, fp32 accum.
// Warp (wm 0..3, wn 0..1): 16x32 out via 4x m16n8k16 atoms. K chunked by 64.
// Columns gate-interleaved: cols 4k..4k+3 = (i,f,g,o) of h-index col0/4 + tx.
__device__ __forceinline__ void lstm_mma_tile(
    const __half* __restrict__ A0, long long lda0, int K0,
    const __half* __restrict__ A1, long long lda1, int K1,
    const __half* __restrict__ W,  int ldw,
    const float* __restrict__ bias,
    float* __restrict__ c, __half* __restrict__ h_out,
    __half* __restrict__ seq_out, long long seq_stride,
    int bx, int by)
{
    extern __shared__ __half sm[];
    __half* As = sm;                   // [2][64][72]
    __half* Ws = sm + 2 * 64 * 72;     // [2][64][72]
    float*  gates = (float*)sm;        // overlay [64][68] (used after K loop)

    const int tid  = threadIdx.x;
    const int w    = tid >> 5;
    const int lane = tid & 31;
    const int grp  = lane >> 2;        // 0..7
    const int tq   = lane & 3;         // 0..3
    const int wm   = w & 3;            // M block (16 rows)
    const int wn   = w >> 2;           // N block (32 cols)
    const int row0 = by * 64, col0 = bx * 64;
    const int nchunks = (K0 + K1) >> 6;
    const int r0l = tid >> 3,         c0l = (tid & 7) * 8;          // ld slot 0
    const int r1l = (tid + 256) >> 3, c1l = ((tid + 256) & 7) * 8;  // ld slot 1

    float acc[4][4];
    #pragma unroll
    for (int j = 0; j < 4; j++)
        #pragma unroll
        for (int i = 0; i < 4; i++) acc[j][i] = 0.f;

    uint4 ra0, ra1, rw0, rw1;

    // prologue: chunk 0 (k=0 always inside A0: K0 >= 64)
    ra0 = *(const uint4*)&A0[(size_t)(row0 + r0l) * lda0 + c0l];
    ra1 = *(const uint4*)&A0[(size_t)(row0 + r1l) * lda0 + c1l];
    rw0 = *(const uint4*)&W [(size_t)(col0 + r0l) * ldw + c0l];
    rw1 = *(const uint4*)&W [(size_t)(col0 + r1l) * ldw + c1l];
    *(uint4*)&As[r0l * 72 + c0l] = ra0;
    *(uint4*)&As[r1l * 72 + c1l] = ra1;
    *(uint4*)&Ws[r0l * 72 + c0l] = rw0;
    *(uint4*)&Ws[r1l * 72 + c1l] = rw1;
    __syncthreads();

    int p = 0;
    for (int ch = 0; ch < nchunks; ch++) {
        const bool more = (ch + 1 < nchunks);
        if (more) {
            const int k0 = (ch + 1) << 6;
            const __half* Aseg; long long ldA; int kk;
            if (k0 < K0) { Aseg = A0; ldA = lda0; kk = k0; }
            else         { Aseg = A1; ldA = lda1; kk = k0 - K0; }
            ra0 = *(const uint4*)&Aseg[(size_t)(row0 + r0l) * ldA + kk + c0l];
            ra1 = *(const uint4*)&Aseg[(size_t)(row0 + r1l) * ldA + kk + c1l];
            rw0 = *(const uint4*)&W[(size_t)(col0 + r0l) * ldw + k0 + c0l];
            rw1 = *(const uint4*)&W[(size_t)(col0 + r1l) * ldw + k0 + c1l];
        }
        const __half* Ab = As + p * 4608 + (wm * 16) * 72;
        const __half* Wb = Ws + p * 4608 + (wn * 32) * 72;
        #pragma unroll
        for (int ks = 0; ks < 4; ks++) {
            const int kb = ks * 16 + 2 * tq;
            uint32_t a0 = *(const uint32_t*)&Ab[(grp    ) * 72 + kb    ];
            uint32_t a1 = *(const uint32_t*)&Ab[(grp + 8) * 72 + kb    ];
            uint32_t a2 = *(const uint32_t*)&Ab[(grp    ) * 72 + kb + 8];
            uint32_t a3 = *(const uint32_t*)&Ab[(grp + 8) * 72 + kb + 8];
            #pragma unroll
            for (int j = 0; j < 4; j++) {
                uint32_t b0 = *(const uint32_t*)&Wb[(j * 8 + grp) * 72 + kb    ];
                uint32_t b1 = *(const uint32_t*)&Wb[(j * 8 + grp) * 72 + kb + 8];
                mma16816(acc[j], a0, a1, a2, a3, b0, b1);
            }
        }
        if (more) {
            const int q = p ^ 1, base = q * 4608;
            *(uint4*)&As[base + r0l * 72 + c0l] = ra0;
            *(uint4*)&As[base + r1l * 72 + c1l] = ra1;
            *(uint4*)&Ws[base + r0l * 72 + c0l] = rw0;
            *(uint4*)&Ws[base + r1l * 72 + c1l] = rw1;
            __syncthreads();
            p = q;
        }
    }

    __syncthreads();   // all mma reads of As/Ws done before gates overlay
    // scatter accumulators: D[m][n] -> gates[m][n], m16n8 atom lane mapping
    #pragma unroll
    for (int j = 0; j < 4; j++) {
        int gcol = wn * 32 + j * 8 + 2 * tq;
        int grow = wm * 16 + grp;
        gates[grow * 68 + gcol]           = acc[j][0];
        gates[grow * 68 + gcol + 1]       = acc[j][1];
        gates[(grow + 8) * 68 + gcol]     = acc[j][2];
        gates[(grow + 8) * 68 + gcol + 1] = acc[j][3];
    }
    __syncthreads();

    // epilogue: thread = 4 rows x 1 h-index (4 interleaved gate cols)
    const int tx = tid & 15, ty = tid >> 4;
    const int hidx = (col0 >> 2) + tx;
    float4 bv = *(const float4*)&bias[col0 + tx * 4];
    #pragma unroll
    for (int rr = 0; rr < 4; rr++) {
        int rloc = ty * 4 + rr;
        int row  = row0 + rloc;
        float4 g = *(float4*)&gates[rloc * 68 + tx * 4];
        float iv = sigf(g.x + bv.x);
        float fv = sigf(g.y + bv.y);
        float gv = tanhf(g.z + bv.z);
        float ov = sigf(g.w + bv.w);
        int ci = row * HH + hidx;
        float cn = fv * c[ci] + iv * gv;
        c[ci] = cn;
        float hv = ov * tanhf(cn);
        h_out[ci] = __float2half(hv);
        if (seq_out) seq_out[(long long)row * seq_stride + hidx] = __float2half(hv);
    }
}

// ---------------- encoder: pipelined layer0(step t) + layer1(step t-1) ------
__global__ __launch_bounds__(256)
void enc_step_kernel(int t)
{
    if (blockIdx.z == 0) {
        if (t >= TT) return;
        lstm_mma_tile(g_x + (size_t)t * DD, (long long)TT * DD, DD,
                      g_h0[t & 1], HH, HH,
                      g_hW0, 320, g_b0,
                      g_c0, g_h0[(t + 1) & 1],
                      g_enc1 + (size_t)t * HH, (long long)TT * HH,
                      blockIdx.x, blockIdx.y);
    } else {
        if (t == 0) return;
        int tt = t - 1;
        lstm_mma_tile(g_enc1 + (size_t)tt * HH, (long long)TT * HH, HH,
                      g_h1[tt & 1], HH, HH,
                      g_hW1, 512, g_b1,
                      g_c1, g_h1[(tt + 1) & 1],
                      g_enc + (size_t)tt * HH, (long long)TT * HH,
                      blockIdx.x, blockIdx.y);
    }
}

// ---------------- decoder attention (online softmax) + p-projection ----------
__global__ __launch_bounds__(256)
void dec_attn_kernel(const float* __restrict__ prev_y, long long ldy,
                     const float* __restrict__ Wp, const float* __restrict__ bp, int s)
{
    int b = blockIdx.x;
    const __half* h = g_h1[s & 1] + b * HH;
    __shared__ float sh_h[HH];
    __shared__ float sh_py[DD];
    __shared__ float sh_m[8], sh_s[8];
    __shared__ float sh_part[8][HH];
    int tid = threadIdx.x, lane = tid & 31, w = tid >> 5;

    sh_h[tid] = __half2float(h[tid]);
    if (tid < DD) sh_py[tid] = prev_y[(long long)b * ldy + tid];
    __syncthreads();

    float m = -1e30f, ssum = 0.f;
    float accv[8];
    #pragma unroll
    for (int c2 = 0; c2 < 8; c2++) accv[c2] = 0.f;
    const __half* ebase = g_enc + (long long)b * TT * HH;

    for (int i = 0; i < 64; i++) {
        int t = w * 64 + i;
        const __half* e = ebase + (long long)t * HH;
        float v[8];
        float dot = 0.f;
        #pragma unroll
        for (int c2 = 0; c2 < 8; c2++) {
            v[c2] = __half2float(e[lane + 32 * c2]);
            dot = fmaf(v[c2], sh_h[lane + 32 * c2], dot);
        }
        #pragma unroll
        for (int o = 16; o > 0; o >>= 1) dot += __shfl_xor_sync(0xffffffffu, dot, o);
        float score = dot * 0.0625f;                 // / sqrt(256)
        float nm  = fmaxf(m, score);
        float esc = __expf(m - nm);
        float pw  = __expf(score - nm);
        ssum = ssum * esc + pw;
        #pragma unroll
        for (int c2 = 0; c2 < 8; c2++) accv[c2] = accv[c2] * esc + pw * v[c2];
        m = nm;
    }
    if (lane == 0) { sh_m[w] = m; sh_s[w] = ssum; }
    #pragma unroll
    for (int c2 = 0; c2 < 8; c2++) sh_part[w][lane + 32 * c2] = accv[c2];
    __syncthreads();

    float M = sh_m[0];
    #pragma unroll
    for (int ww = 1; ww < 8; ww++) M = fmaxf(M, sh_m[ww]);
    float num = 0.f, den = 0.f;
    #pragma unroll
    for (int ww = 0; ww < 8; ww++) {
        float f = __expf(sh_m[ww] - M);
        den += f * sh_s[ww];
        num += f * sh_part[ww][tid];
    }
    g_inp[b * 512 + 256 + tid] = __float2half(num / den);     // ctx

    float pv = bp[tid];
    #pragma unroll 8
    for (int d = 0; d < DD; d++) pv = fmaf(sh_py[d], Wp[tid * DD + d], pv);
    g_inp[b * 512 + tid] = __float2half(pv);                  // prev_y @ Wp^T + bp
}

// ---------------- decoder LSTM cell ----------------
__global__ __launch_bounds__(256)
void dec_lstm_kernel(int s)
{
    lstm_mma_tile(g_inp, 512, 512,
                  g_h1[s & 1], HH, HH,
                  g_hWd, 768, g_bd,
                  g_c1, g_h1[(s + 1) & 1],
                  nullptr, 0,
                  blockIdx.x, blockIdx.y);
}

// ---------------- decoder output: y = [h_new | ctx] @ Wo^T + bo --------------
__global__ __launch_bounds__(256)
void dec_y_kernel(float* __restrict__ out, const float* __restrict__ Wo,
                  const float* __restrict__ bo, int s)
{
    __shared__ float sA[16][512];
    int tid = threadIdx.x;
    int rb = blockIdx.x * 16;
    const __half* hN = g_h1[(s + 1) & 1];
    for (int i = tid; i < 16 * 512; i += 256) {
        int r = i >> 9, k = i & 511;
        sA[r][k] = (k < 256) ? __half2float(hN[(rb + r) * HH + k])
                             : __half2float(g_inp[(rb + r) * 512 + k]);
    }
    __syncthreads();
    int j  = tid & 63;
    int r0 = (tid >> 6) * 4;
    float a0 = bo[j], a1 = a0, a2 = a0, a3 = a0;
    const float4* Wrow = reinterpret_cast<const float4*>(Wo + j * 512);
    for (int k4 = 0; k4 < 128; k4++) {
        float4 wv = Wrow[k4];
        int k = k4 * 4;
        a0 = fmaf(wv.x, sA[r0+0][k], a0); a0 = fmaf(wv.y, sA[r0+0][k+1], a0);
        a0 = fmaf(wv.z, sA[r0+0][k+2], a0); a0 = fmaf(wv.w, sA[r0+0][k+3], a0);
        a1 = fmaf(wv.x, sA[r0+1][k], a1); a1 = fmaf(wv.y, sA[r0+1][k+1], a1);
        a1 = fmaf(wv.z, sA[r0+1][k+2], a1); a1 = fmaf(wv.w, sA[r0+1][k+3], a1);
        a2 = fmaf(wv.x, sA[r0+2][k], a2); a2 = fmaf(wv.y, sA[r0+2][k+1], a2);
        a2 = fmaf(wv.z, sA[r0+2][k+2], a2); a2 = fmaf(wv.w, sA[r0+2][k+3], a2);
        a3 = fmaf(wv.x, sA[r0+3][k], a3); a3 = fmaf(wv.y, sA[r0+3][k+1], a3);
        a3 = fmaf(wv.z, sA[r0+3][k+2], a3); a3 = fmaf(wv.w, sA[r0+3][k+3], a3);
    }
    long long base = ((long long)(rb + r0) * WOUT + s) * DD + j;
    out[base]                        = a0;
    out[base + 1LL * WOUT * DD]      = a1;
    out[base + 2LL * WOUT * DD]      = a2;
    out[base + 3LL * WOUT * DD]      = a3;
}

// ---------------- launch ----------------
extern "C" void kernel_launch(void* const* d_in, const int* in_sizes, int n_in,
                              void* d_out, int out_size)
{
    const float* x_in = (const float*)d_in[0];
    int o = (n_in > 1 && in_sizes[1] == 1) ? 2 : 1;
    const float* Wih0 = (const float*)d_in[o + 0];
    const float* Whh0 = (const float*)d_in[o + 1];
    const float* bih0 = (const float*)d_in[o + 2];
    const float* bhh0 = (const float*)d_in[o + 3];
    const float* Wih1 = (const float*)d_in[o + 4];
    const float* Whh1 = (const float*)d_in[o + 5];
    const float* bih1 = (const float*)d_in[o + 6];
    const float* bhh1 = (const float*)d_in[o + 7];
    const float* Wihd = (const float*)d_in[o + 8];
    const float* Whhd = (const float*)d_in[o + 9];
    const float* bihd = (const float*)d_in[o + 10];
    const float* bhhd = (const float*)d_in[o + 11];
    const float* Wp   = (const float*)d_in[o + 12];
    const float* bp   = (const float*)d_in[o + 13];
    const float* Wo   = (const float*)d_in[o + 14];
    const float* bo   = (const float*)d_in[o + 15];
    float* out = (float*)d_out;

    const int smem = (2 * 64 * 72 * 2) * 2;   // 36864 B: As + Ws, double buffered

    prep_kernel<<<GG, 256>>>(Wih0, Whh0, bih0, bhh0,
                             Wih1, Whh1, bih1, bhh1,
                             Wihd, Whhd, bihd, bhhd);
    xconv_kernel<<<(BB * TT * DD + 255) / 256, 256>>>(x_in);

    // encoder: pipelined two-layer scan, 513 launches, 128 blocks each
    for (int t = 0; t <= TT; t++)
        enc_step_kernel<<<dim3(16, 4, 2), 256, smem>>>(t);

    // decoder: 96 steps
    for (int s = 0; s < WOUT; s++) {
        const float* py = (s == 0) ? (x_in + (long long)(TT - 1) * DD)
                                   : (out + (long long)(s - 1) * DD);
        long long ldy = (s == 0) ? (long long)TT * DD : (long long)WOUT * DD;
        dec_attn_kernel<<<BB, 256>>>(py, ldy, Wp, bp, s);
        dec_lstm_kernel<<<dim3(16, 4), 256, smem>>>(s);
        dec_y_kernel<<<16, 256>>>(out, Wo, bo, s);
    }
}

// round 11
// speedup vs baseline: 3.0297x; 1.0321x over previous
#include <cuda_runtime.h>
#include <cuda_fp16.h>
#include <cuda_bf16.h>
#include <cstdint>

// Problem constants
#define DD   64      // input dim
#define HH   256     // hidden dim
#define BB   256     // batch
#define TT   512     // encoder timesteps
#define GG   1024    // 4*H
#define WOUT 96      // decoder steps

// ---------------- static scratch (no cudaMalloc allowed) ----------------
__device__ __half g_hW0[GG * 320];          // fp16 gate-permuted [p][0:64]=Wih0,[64:320]=Whh0
__device__ float  g_b0[GG];
__device__ __half g_hW1[GG * 512];          // [p][0:256]=Wih1, [256:512]=Whh1
__device__ float  g_b1[GG];
__device__ __half g_hWd[GG * 768];          // [p][0:512]=Wih_d, [512:768]=Whh_d
__device__ float  g_bd[GG];
__device__ __half g_x   [(size_t)BB * TT * DD];   // x_in fp16
__device__ __half g_enc1[(size_t)BB * TT * HH];   // layer-0 outputs fp16
__device__ __half g_enc [(size_t)BB * TT * HH];   // layer-1 outputs fp16
__device__ __half g_h0[2][BB * HH];
__device__ __half g_h1[2][BB * HH];
__device__ float  g_c1[BB * HH];
__device__ __half g_inp[BB * 512];          // decoder [p | ctx] fp16

__device__ unsigned g_bar_cnt;
__device__ volatile unsigned g_bar_phase;

// ---------------- prep: gate-interleave + fp16 weights, zero state ----------
// permuted row p = 4k+q  <-  original row q*H + k
__global__ void prep_kernel(
    const float* __restrict__ Wih0, const float* __restrict__ Whh0,
    const float* __restrict__ bih0, const float* __restrict__ bhh0,
    const float* __restrict__ Wih1, const float* __restrict__ Whh1,
    const float* __restrict__ bih1, const float* __restrict__ bhh1,
    const float* __restrict__ Wihd, const float* __restrict__ Whhd,
    const float* __restrict__ bihd, const float* __restrict__ bhhd)
{
    int p = blockIdx.x;          // 0..1023
    int k = p >> 2, q = p & 3;
    int r = q * HH + k;
    int tid = threadIdx.x;       // 256 threads

    if (tid < 64) g_hW0[p * 320 + tid] = __float2half(Wih0[r * 64 + tid]);
    g_hW0[p * 320 +  64 + tid] = __float2half(Whh0[r * 256 + tid]);

    g_hW1[p * 512 +       tid] = __float2half(Wih1[r * 256 + tid]);
    g_hW1[p * 512 + 256 + tid] = __float2half(Whh1[r * 256 + tid]);

    g_hWd[p * 768 +       tid] = __float2half(Wihd[r * 512 + tid]);
    g_hWd[p * 768 + 256 + tid] = __float2half(Wihd[r * 512 + 256 + tid]);
    g_hWd[p * 768 + 512 + tid] = __float2half(Whhd[r * 256 + tid]);

    if (tid == 0) {
        g_b0[p] = bih0[r] + bhh0[r];
        g_b1[p] = bih1[r] + bhh1[r];
        g_bd[p] = bihd[r] + bhhd[r];
        if (p == 0) { g_bar_cnt = 0; g_bar_phase = 0; }
    }
    int idx = p * 256 + tid;     // covers 262144 >= 65536
    if (idx < BB * HH) {
        g_h0[0][idx] = __float2half(0.f); g_h0[1][idx] = __float2half(0.f);
        g_h1[0][idx] = __float2half(0.f); g_h1[1][idx] = __float2half(0.f);
        g_c1[idx] = 0.f;
    }
}

__global__ void xconv_kernel(const float* __restrict__ x)
{
    size_t i = (size_t)blockIdx.x * blockDim.x + threadIdx.x;
    if (i < (size_t)BB * TT * DD) g_x[i] = __float2half(x[i]);
}

__device__ __forceinline__ float sigf(float x) { return 1.f / (1.f + expf(-x)); }

// One HMMA atom: D(16x8) += A(16x16,row) * B(16x8,col), fp16 in, fp32 accum.
__device__ __forceinline__ void mma16816(float* cc,
                                         uint32_t a0, uint32_t a1, uint32_t a2, uint32_t a3,
                                         uint32_t b0, uint32_t b1)
{
    asm volatile(
        "mma.sync.aligned.m16n8k16.row.col.f32.f16.f16.f32 "
        "{%0,%1,%2,%3}, {%4,%5,%6,%7}, {%8,%9}, {%0,%1,%2,%3};"
        : "+f"(cc[0]), "+f"(cc[1]), "+f"(cc[2]), "+f"(cc[3])
        : "r"(a0), "r"(a1), "r"(a2), "r"(a3), "r"(b0), "r"(b1));
}

// ---------------- grid barrier (sense-reversing; fence drops stale L1) -------
__device__ __forceinline__ void gridbar(unsigned* phase)
{
    __syncthreads();
    if (threadIdx.x == 0) {
        unsigned p = *phase;
        __threadfence();                              // publish our writes
        if (atomicAdd(&g_bar_cnt, 1u) == (unsigned)gridDim.x - 1u) {
            atomicExch(&g_bar_cnt, 0u);
            __threadfence();
            g_bar_phase = p + 1u;
        } else {
            while (g_bar_phase == p) { __nanosleep(32); }
        }
        __threadfence();                              // invalidate L1
        *phase = p + 1u;
    }
    __syncthreads();
}

// ---------------- persistent encoder body (one layer, one 64x64 tile) --------
// Weights resident in smem for whole scan; c-state in registers; HMMA core.
template<int LAYER>
__device__ __forceinline__ void enc_persist_body(int ct, int rt)
{
    constexpr int KTOT = (LAYER == 0) ? 320 : 512;
    constexpr int AST  = KTOT + 8;        // smem row stride (halves); bank-safe
    constexpr int NU4  = KTOT / 8;        // uint4 per row

    extern __shared__ __half sm[];
    __half* As    = sm;                   // [64][AST]
    __half* Ws    = sm + 64 * AST;        // [64][AST], persistent
    float*  gates = (float*)sm;           // overlay on As after MMA

    const int tid  = threadIdx.x;
    const int w    = tid >> 5;
    const int lane = tid & 31;
    const int grp  = lane >> 2;
    const int tq   = lane & 3;
    const int wm   = w & 3;
    const int wn   = w >> 2;
    const int row0 = rt * 64, col0 = ct * 64;
    const int tx = tid & 15, ty = tid >> 4;
    const int hidx = ct * 16 + tx;

    const __half* Wg   = (LAYER == 0) ? g_hW0 : g_hW1;
    const float*  bias = (LAYER == 0) ? g_b0  : g_b1;

    // load W tile into smem once
    for (int i = tid; i < 64 * NU4; i += 256) {
        int cc = i / NU4, k = (i % NU4) * 8;
        *(uint4*)&Ws[cc * AST + k] = *(const uint4*)&Wg[(size_t)(col0 + cc) * KTOT + k];
    }
    float4 bv = *(const float4*)&bias[col0 + tx * 4];
    float cst[4] = {0.f, 0.f, 0.f, 0.f};

    unsigned phase = 0;
    __syncthreads();

    for (int e = 0; e <= TT; e++) {
        const bool active = (LAYER == 0) ? (e < TT) : (e >= 1);
        if (active) {
            const int t = (LAYER == 0) ? e : (e - 1);
            const __half* __restrict__ hprev = (LAYER == 0) ? g_h0[t & 1] : g_h1[t & 1];
            // As load: [x | h] or [enc1 | h]
            for (int i = tid; i < 64 * NU4; i += 256) {
                int r = i / NU4, k = (i % NU4) * 8;
                const __half* src;
                if (LAYER == 0)
                    src = (k < 64) ? &g_x[((size_t)(row0 + r) * TT + t) * DD + k]
                                   : &hprev[(row0 + r) * HH + k - 64];
                else
                    src = (k < 256) ? &g_enc1[((size_t)(row0 + r) * TT + t) * HH + k]
                                    : &hprev[(row0 + r) * HH + k - 256];
                *(uint4*)&As[r * AST + k] = *(const uint4*)src;
            }
            __syncthreads();

            // HMMA: warp tile 16x32 via 4 m16n8k16 atoms per k-step
            float acc[4][4];
            #pragma unroll
            for (int j = 0; j < 4; j++)
                #pragma unroll
                for (int i2 = 0; i2 < 4; i2++) acc[j][i2] = 0.f;
            const __half* Ab = As + (wm * 16) * AST;
            const __half* Wb = Ws + (wn * 32) * AST;
            #pragma unroll 4
            for (int ks = 0; ks < KTOT / 16; ks++) {
                const int kb = ks * 16 + 2 * tq;
                uint32_t a0 = *(const uint32_t*)&Ab[(grp    ) * AST + kb    ];
                uint32_t a1 = *(const uint32_t*)&Ab[(grp + 8) * AST + kb    ];
                uint32_t a2 = *(const uint32_t*)&Ab[(grp    ) * AST + kb + 8];
                uint32_t a3 = *(const uint32_t*)&Ab[(grp + 8) * AST + kb + 8];
                #pragma unroll
                for (int j = 0; j < 4; j++) {
                    uint32_t b0 = *(const uint32_t*)&Wb[(j * 8 + grp) * AST + kb    ];
                    uint32_t b1 = *(const uint32_t*)&Wb[(j * 8 + grp) * AST + kb + 8];
                    mma16816(acc[j], a0, a1, a2, a3, b0, b1);
                }
            }
            __syncthreads();   // As reads done; safe to overlay gates

            #pragma unroll
            for (int j = 0; j < 4; j++) {
                int gcol = wn * 32 + j * 8 + 2 * tq;
                int grow = wm * 16 + grp;
                gates[grow * 68 + gcol]           = acc[j][0];
                gates[grow * 68 + gcol + 1]       = acc[j][1];
                gates[(grow + 8) * 68 + gcol]     = acc[j][2];
                gates[(grow + 8) * 68 + gcol + 1] = acc[j][3];
            }
            __syncthreads();

            // fused LSTM epilogue; c-state in registers
            __half* __restrict__ hnew = (LAYER == 0) ? g_h0[(t + 1) & 1] : g_h1[(t + 1) & 1];
            #pragma unroll
            for (int rr = 0; rr < 4; rr++) {
                int rloc = ty * 4 + rr;
                int row  = row0 + rloc;
                float4 g = *(float4*)&gates[rloc * 68 + tx * 4];
                float iv = sigf(g.x + bv.x);
                float fv = sigf(g.y + bv.y);
                float gv = tanhf(g.z + bv.z);
                float ov = sigf(g.w + bv.w);
                float cn = fv * cst[rr] + iv * gv;
                cst[rr] = cn;
                float hv = ov * tanhf(cn);
                __half hh = __float2half(hv);
                hnew[row * HH + hidx] = hh;
                if (LAYER == 0) {
                    g_enc1[((size_t)row * TT + t) * HH + hidx] = hh;
                } else {
                    g_enc[((size_t)row * TT + t) * HH + hidx] = hh;
                    if (t == TT - 1) g_c1[row * HH + hidx] = cn;
                }
            }
        }
        if (e < TT) gridbar(&phase);
    }
}

__global__ __launch_bounds__(256, 1)
void enc_persist_kernel()
{
    int blk = blockIdx.x;
    int sub = blk & 63;
    int ct = sub & 15, rt = sub >> 4;
    if ((blk >> 6) == 0) enc_persist_body<0>(ct, rt);
    else                 enc_persist_body<1>(ct, rt);
}

// ---------------- fused HMMA GEMM + LSTM-cell (decoder cell, R10-proven) -----
__device__ __forceinline__ void lstm_mma_tile(
    const __half* __restrict__ A0, long long lda0, int K0,
    const __half* __restrict__ A1, long long lda1, int K1,
    const __half* __restrict__ W,  int ldw,
    const float* __restrict__ bias,
    float* __restrict__ c, __half* __restrict__ h_out,
    int bx, int by)
{
    extern __shared__ __half sm[];
    __half* As = sm;                   // [2][64][72]
    __half* Ws = sm + 2 * 64 * 72;     // [2][64][72]
    float*  gates = (float*)sm;        // overlay [64][68]

    const int tid  = threadIdx.x;
    const int w    = tid >> 5;
    const int lane = tid & 31;
    const int grp  = lane >> 2;
    const int tq   = lane & 3;
    const int wm   = w & 3;
    const int wn   = w >> 2;
    const int row0 = by * 64, col0 = bx * 64;
    const int nchunks = (K0 + K1) >> 6;
    const int r0l = tid >> 3,         c0l = (tid & 7) * 8;
    const int r1l = (tid + 256) >> 3, c1l = ((tid + 256) & 7) * 8;

    float acc[4][4];
    #pragma unroll
    for (int j = 0; j < 4; j++)
        #pragma unroll
        for (int i = 0; i < 4; i++) acc[j][i] = 0.f;

    uint4 ra0, ra1, rw0, rw1;

    ra0 = *(const uint4*)&A0[(size_t)(row0 + r0l) * lda0 + c0l];
    ra1 = *(const uint4*)&A0[(size_t)(row0 + r1l) * lda0 + c1l];
    rw0 = *(const uint4*)&W [(size_t)(col0 + r0l) * ldw + c0l];
    rw1 = *(const uint4*)&W [(size_t)(col0 + r1l) * ldw + c1l];
    *(uint4*)&As[r0l * 72 + c0l] = ra0;
    *(uint4*)&As[r1l * 72 + c1l] = ra1;
    *(uint4*)&Ws[r0l * 72 + c0l] = rw0;
    *(uint4*)&Ws[r1l * 72 + c1l] = rw1;
    __syncthreads();

    int p = 0;
    for (int ch = 0; ch < nchunks; ch++) {
        const bool more = (ch + 1 < nchunks);
        if (more) {
            const int k0 = (ch + 1) << 6;
            const __half* Aseg; long long ldA; int kk;
            if (k0 < K0) { Aseg = A0; ldA = lda0; kk = k0; }
            else         { Aseg = A1; ldA = lda1; kk = k0 - K0; }
            ra0 = *(const uint4*)&Aseg[(size_t)(row0 + r0l) * ldA + kk + c0l];
            ra1 = *(const uint4*)&Aseg[(size_t)(row0 + r1l) * ldA + kk + c1l];
            rw0 = *(const uint4*)&W[(size_t)(col0 + r0l) * ldw + k0 + c0l];
            rw1 = *(const uint4*)&W[(size_t)(col0 + r1l) * ldw + k0 + c1l];
        }
        const __half* Ab = As + p * 4608 + (wm * 16) * 72;
        const __half* Wb = Ws + p * 4608 + (wn * 32) * 72;
        #pragma unroll
        for (int ks = 0; ks < 4; ks++) {
            const int kb = ks * 16 + 2 * tq;
            uint32_t a0 = *(const uint32_t*)&Ab[(grp    ) * 72 + kb    ];
            uint32_t a1 = *(const uint32_t*)&Ab[(grp + 8) * 72 + kb    ];
            uint32_t a2 = *(const uint32_t*)&Ab[(grp    ) * 72 + kb + 8];
            uint32_t a3 = *(const uint32_t*)&Ab[(grp + 8) * 72 + kb + 8];
            #pragma unroll
            for (int j = 0; j < 4; j++) {
                uint32_t b0 = *(const uint32_t*)&Wb[(j * 8 + grp) * 72 + kb    ];
                uint32_t b1 = *(const uint32_t*)&Wb[(j * 8 + grp) * 72 + kb + 8];
                mma16816(acc[j], a0, a1, a2, a3, b0, b1);
            }
        }
        if (more) {
            const int q = p ^ 1, base = q * 4608;
            *(uint4*)&As[base + r0l * 72 + c0l] = ra0;
            *(uint4*)&As[base + r1l * 72 + c1l] = ra1;
            *(uint4*)&Ws[base + r0l * 72 + c0l] = rw0;
            *(uint4*)&Ws[base + r1l * 72 + c1l] = rw1;
            __syncthreads();
            p = q;
        }
    }

    __syncthreads();
    #pragma unroll
    for (int j = 0; j < 4; j++) {
        int gcol = wn * 32 + j * 8 + 2 * tq;
        int grow = wm * 16 + grp;
        gates[grow * 68 + gcol]           = acc[j][0];
        gates[grow * 68 + gcol + 1]       = acc[j][1];
        gates[(grow + 8) * 68 + gcol]     = acc[j][2];
        gates[(grow + 8) * 68 + gcol + 1] = acc[j][3];
    }
    __syncthreads();

    const int tx = tid & 15, ty = tid >> 4;
    const int hidx = (col0 >> 2) + tx;
    float4 bv = *(const float4*)&bias[col0 + tx * 4];
    #pragma unroll
    for (int rr = 0; rr < 4; rr++) {
        int rloc = ty * 4 + rr;
        int row  = row0 + rloc;
        float4 g = *(float4*)&gates[rloc * 68 + tx * 4];
        float iv = sigf(g.x + bv.x);
        float fv = sigf(g.y + bv.y);
        float gv = tanhf(g.z + bv.z);
        float ov = sigf(g.w + bv.w);
        int ci = row * HH + hidx;
        float cn = fv * c[ci] + iv * gv;
        c[ci] = cn;
        h_out[ci] = __float2half(ov * tanhf(cn));
    }
}

// ---------------- decoder attention (online softmax) + p-projection ----------
__global__ __launch_bounds__(256)
void dec_attn_kernel(const float* __restrict__ prev_y, long long ldy,
                     const float* __restrict__ Wp, const float* __restrict__ bp, int s)
{
    int b = blockIdx.x;
    const __half* h = g_h1[s & 1] + b * HH;
    __shared__ float sh_h[HH];
    __shared__ float sh_py[DD];
    __shared__ float sh_m[8], sh_s[8];
    __shared__ float sh_part[8][HH];
    int tid = threadIdx.x, lane = tid & 31, w = tid >> 5;

    sh_h[tid] = __half2float(h[tid]);
    if (tid < DD) sh_py[tid] = prev_y[(long long)b * ldy + tid];
    __syncthreads();

    float m = -1e30f, ssum = 0.f;
    float accv[8];
    #pragma unroll
    for (int c2 = 0; c2 < 8; c2++) accv[c2] = 0.f;
    const __half* ebase = g_enc + (long long)b * TT * HH;

    for (int i = 0; i < 64; i++) {
        int t = w * 64 + i;
        const __half* e = ebase + (long long)t * HH;
        float v[8];
        float dot = 0.f;
        #pragma unroll
        for (int c2 = 0; c2 < 8; c2++) {
            v[c2] = __half2float(e[lane + 32 * c2]);
            dot = fmaf(v[c2], sh_h[lane + 32 * c2], dot);
        }
        #pragma unroll
        for (int o = 16; o > 0; o >>= 1) dot += __shfl_xor_sync(0xffffffffu, dot, o);
        float score = dot * 0.0625f;                 // / sqrt(256)
        float nm  = fmaxf(m, score);
        float esc = __expf(m - nm);
        float pw  = __expf(score - nm);
        ssum = ssum * esc + pw;
        #pragma unroll
        for (int c2 = 0; c2 < 8; c2++) accv[c2] = accv[c2] * esc + pw * v[c2];
        m = nm;
    }
    if (lane == 0) { sh_m[w] = m; sh_s[w] = ssum; }
    #pragma unroll
    for (int c2 = 0; c2 < 8; c2++) sh_part[w][lane + 32 * c2] = accv[c2];
    __syncthreads();

    float M = sh_m[0];
    #pragma unroll
    for (int ww = 1; ww < 8; ww++) M = fmaxf(M, sh_m[ww]);
    float num = 0.f, den = 0.f;
    #pragma unroll
    for (int ww = 0; ww < 8; ww++) {
        float f = __expf(sh_m[ww] - M);
        den += f * sh_s[ww];
        num += f * sh_part[ww][tid];
    }
    g_inp[b * 512 + 256 + tid] = __float2half(num / den);     // ctx

    float pv = bp[tid];
    #pragma unroll 8
    for (int d = 0; d < DD; d++) pv = fmaf(sh_py[d], Wp[tid * DD + d], pv);
    g_inp[b * 512 + tid] = __float2half(pv);                  // prev_y @ Wp^T + bp
}

// ---------------- decoder LSTM cell ----------------
__global__ __launch_bounds__(256)
void dec_lstm_kernel(int s)
{
    lstm_mma_tile(g_inp, 512, 512,
                  g_h1[s & 1], HH, HH,
                  g_hWd, 768, g_bd,
                  g_c1, g_h1[(s + 1) & 1],
                  blockIdx.x, blockIdx.y);
}

// ---------------- decoder output: y = [h_new | ctx] @ Wo^T + bo --------------
__global__ __launch_bounds__(256)
void dec_y_kernel(float* __restrict__ out, const float* __restrict__ Wo,
                  const float* __restrict__ bo, int s)
{
    __shared__ float sA[16][512];
    int tid = threadIdx.x;
    int rb = blockIdx.x * 16;
    const __half* hN = g_h1[(s + 1) & 1];
    for (int i = tid; i < 16 * 512; i += 256) {
        int r = i >> 9, k = i & 511;
        sA[r][k] = (k < 256) ? __half2float(hN[(rb + r) * HH + k])
                             : __half2float(g_inp[(rb + r) * 512 + k]);
    }
    __syncthreads();
    int j  = tid & 63;
    int r0 = (tid >> 6) * 4;
    float a0 = bo[j], a1 = a0, a2 = a0, a3 = a0;
    const float4* Wrow = reinterpret_cast<const float4*>(Wo + j * 512);
    for (int k4 = 0; k4 < 128; k4++) {
        float4 wv = Wrow[k4];
        int k = k4 * 4;
        a0 = fmaf(wv.x, sA[r0+0][k], a0); a0 = fmaf(wv.y, sA[r0+0][k+1], a0);
        a0 = fmaf(wv.z, sA[r0+0][k+2], a0); a0 = fmaf(wv.w, sA[r0+0][k+3], a0);
        a1 = fmaf(wv.x, sA[r0+1][k], a1); a1 = fmaf(wv.y, sA[r0+1][k+1], a1);
        a1 = fmaf(wv.z, sA[r0+1][k+2], a1); a1 = fmaf(wv.w, sA[r0+1][k+3], a1);
        a2 = fmaf(wv.x, sA[r0+2][k], a2); a2 = fmaf(wv.y, sA[r0+2][k+1], a2);
        a2 = fmaf(wv.z, sA[r0+2][k+2], a2); a2 = fmaf(wv.w, sA[r0+2][k+3], a2);
        a3 = fmaf(wv.x, sA[r0+3][k], a3); a3 = fmaf(wv.y, sA[r0+3][k+1], a3);
        a3 = fmaf(wv.z, sA[r0+3][k+2], a3); a3 = fmaf(wv.w, sA[r0+3][k+3], a3);
    }
    long long base = ((long long)(rb + r0) * WOUT + s) * DD + j;
    out[base]                        = a0;
    out[base + 1LL * WOUT * DD]      = a1;
    out[base + 2LL * WOUT * DD]      = a2;
    out[base + 3LL * WOUT * DD]      = a3;
}

// ---------------- launch ----------------
extern "C" void kernel_launch(void* const* d_in, const int* in_sizes, int n_in,
                              void* d_out, int out_size)
{
    const float* x_in = (const float*)d_in[0];
    int o = (n_in > 1 && in_sizes[1] == 1) ? 2 : 1;
    const float* Wih0 = (const float*)d_in[o + 0];
    const float* Whh0 = (const float*)d_in[o + 1];
    const float* bih0 = (const float*)d_in[o + 2];
    const float* bhh0 = (const float*)d_in[o + 3];
    const float* Wih1 = (const float*)d_in[o + 4];
    const float* Whh1 = (const float*)d_in[o + 5];
    const float* bih1 = (const float*)d_in[o + 6];
    const float* bhh1 = (const float*)d_in[o + 7];
    const float* Wihd = (const float*)d_in[o + 8];
    const float* Whhd = (const float*)d_in[o + 9];
    const float* bihd = (const float*)d_in[o + 10];
    const float* bhhd = (const float*)d_in[o + 11];
    const float* Wp   = (const float*)d_in[o + 12];
    const float* bp   = (const float*)d_in[o + 13];
    const float* Wo   = (const float*)d_in[o + 14];
    const float* bo   = (const float*)d_in[o + 15];
    float* out = (float*)d_out;

    const int smem_enc = 2 * 64 * 520 * 2;   // 133120 B: As + Ws (layer-1 worst case)
    const int smem_dec = (2 * 64 * 72 * 2) * 2;   // 36864 B
    cudaFuncSetAttribute(enc_persist_kernel,
                         cudaFuncAttributeMaxDynamicSharedMemorySize, smem_enc);

    prep_kernel<<<GG, 256>>>(Wih0, Whh0, bih0, bhh0,
                             Wih1, Whh1, bih1, bhh1,
                             Wihd, Whhd, bihd, bhhd);
    xconv_kernel<<<(BB * TT * DD + 255) / 256, 256>>>(x_in);

    // persistent two-layer encoder scan: ONE launch
    enc_persist_kernel<<<128, 256, smem_enc>>>();

    // decoder: 96 steps
    for (int s = 0; s < WOUT; s++) {
        const float* py = (s == 0) ? (x_in + (long long)(TT - 1) * DD)
                                   : (out + (long long)(s - 1) * DD);
        long long ldy = (s == 0) ? (long long)TT * DD : (long long)WOUT * DD;
        dec_attn_kernel<<<BB, 256>>>(py, ldy, Wp, bp, s);
        dec_lstm_kernel<<<dim3(16, 4), 256, smem_dec>>>(s);
        dec_y_kernel<<<16, 256>>>(out, Wo, bo, s);
    }
}

// round 13
// speedup vs baseline: 3.3481x; 1.1051x over previous
#include <cuda_runtime.h>
#include <cuda_fp16.h>
#include <cuda_bf16.h>
#include <cstdint>

// Problem constants
#define DD   64      // input dim
#define HH   256     // hidden dim
#define BB   256     // batch
#define TT   512     // encoder timesteps
#define GG   1024    // 4*H
#define WOUT 96      // decoder steps

// ---------------- static scratch (no cudaMalloc allowed) ----------------
__device__ __half g_hW0[GG * 320];          // fp16 gate-permuted [p][0:64]=Wih0,[64:320]=Whh0
__device__ float  g_b0[GG];
__device__ __half g_hW1[GG * 512];          // [p][0:256]=Wih1, [256:512]=Whh1
__device__ float  g_b1[GG];
__device__ __half g_hWd[GG * 768];          // [p][0:512]=Wih_d, [512:768]=Whh_d
__device__ float  g_bd[GG];
__device__ __half g_x   [(size_t)BB * TT * DD];   // x_in fp16
__device__ __half g_enc1[(size_t)BB * TT * HH];   // layer-0 outputs fp16
__device__ __half g_enc [(size_t)BB * TT * HH];   // layer-1 outputs fp16
__device__ __half g_h0[2][BB * HH];
__device__ __half g_h1[2][BB * HH];
__device__ float  g_c1[BB * HH];
__device__ __half g_inp[BB * 512];          // decoder [p | ctx] fp16

__device__ unsigned g_bar_cnt;
__device__ volatile unsigned g_bar_phase;

// ---------------- prep: gate-interleave + fp16 weights, zero state ----------
// permuted row p = 4k+q  <-  original row q*H + k
__global__ void prep_kernel(
    const float* __restrict__ Wih0, const float* __restrict__ Whh0,
    const float* __restrict__ bih0, const float* __restrict__ bhh0,
    const float* __restrict__ Wih1, const float* __restrict__ Whh1,
    const float* __restrict__ bih1, const float* __restrict__ bhh1,
    const float* __restrict__ Wihd, const float* __restrict__ Whhd,
    const float* __restrict__ bihd, const float* __restrict__ bhhd)
{
    int p = blockIdx.x;          // 0..1023
    int k = p >> 2, q = p & 3;
    int r = q * HH + k;
    int tid = threadIdx.x;       // 256 threads

    if (tid < 64) g_hW0[p * 320 + tid] = __float2half(Wih0[r * 64 + tid]);
    g_hW0[p * 320 +  64 + tid] = __float2half(Whh0[r * 256 + tid]);

    g_hW1[p * 512 +       tid] = __float2half(Wih1[r * 256 + tid]);
    g_hW1[p * 512 + 256 + tid] = __float2half(Whh1[r * 256 + tid]);

    g_hWd[p * 768 +       tid] = __float2half(Wihd[r * 512 + tid]);
    g_hWd[p * 768 + 256 + tid] = __float2half(Wihd[r * 512 + 256 + tid]);
    g_hWd[p * 768 + 512 + tid] = __float2half(Whhd[r * 256 + tid]);

    if (tid == 0) {
        g_b0[p] = bih0[r] + bhh0[r];
        g_b1[p] = bih1[r] + bhh1[r];
        g_bd[p] = bihd[r] + bhhd[r];
        if (p == 0) { g_bar_cnt = 0; g_bar_phase = 0; }
    }
    int idx = p * 256 + tid;     // covers 262144 >= 65536
    if (idx < BB * HH) {
        g_h0[0][idx] = __float2half(0.f); g_h0[1][idx] = __float2half(0.f);
        g_h1[0][idx] = __float2half(0.f); g_h1[1][idx] = __float2half(0.f);
        g_c1[idx] = 0.f;
    }
}

__global__ void xconv_kernel(const float* __restrict__ x)
{
    size_t i = (size_t)blockIdx.x * blockDim.x + threadIdx.x;
    if (i < (size_t)BB * TT * DD) g_x[i] = __float2half(x[i]);
}

__device__ __forceinline__ float sigf(float x) { return 1.f / (1.f + expf(-x)); }

// One HMMA atom: D(16x8) += A(16x16,row) * B(16x8,col), fp16 in, fp32 accum.
__device__ __forceinline__ void mma16816(float* cc,
                                         uint32_t a0, uint32_t a1, uint32_t a2, uint32_t a3,
                                         uint32_t b0, uint32_t b1)
{
    asm volatile(
        "mma.sync.aligned.m16n8k16.row.col.f32.f16.f16.f32 "
        "{%0,%1,%2,%3}, {%4,%5,%6,%7}, {%8,%9}, {%0,%1,%2,%3};"
        : "+f"(cc[0]), "+f"(cc[1]), "+f"(cc[2]), "+f"(cc[3])
        : "r"(a0), "r"(a1), "r"(a2), "r"(a3), "r"(b0), "r"(b1));
}

// ---------------- grid barrier (sense-reversing; fence drops stale L1) -------
__device__ __forceinline__ void gridbar(unsigned* phase)
{
    __syncthreads();
    if (threadIdx.x == 0) {
        unsigned p = *phase;
        __threadfence();                              // publish our writes
        if (atomicAdd(&g_bar_cnt, 1u) == (unsigned)gridDim.x - 1u) {
            atomicExch(&g_bar_cnt, 0u);
            __threadfence();
            g_bar_phase = p + 1u;
        } else {
            while (g_bar_phase == p) { __nanosleep(32); }
        }
        __threadfence();                              // invalidate L1
        *phase = p + 1u;
    }
    __syncthreads();
}

// ---------------- persistent encoder body (one layer, one 64x64 tile) --------
// Weights resident in smem for whole scan; c-state in registers; HMMA core.
template<int LAYER>
__device__ __forceinline__ void enc_persist_body(int ct, int rt)
{
    constexpr int KTOT = (LAYER == 0) ? 320 : 512;
    constexpr int AST  = KTOT + 8;        // smem row stride (halves); bank-safe
    constexpr int NU4  = KTOT / 8;        // uint4 per row

    extern __shared__ __half sm[];
    __half* As    = sm;                   // [64][AST]
    __half* Ws    = sm + 64 * AST;        // [64][AST], persistent
    float*  gates = (float*)sm;           // overlay on As after MMA

    const int tid  = threadIdx.x;
    const int w    = tid >> 5;
    const int lane = tid & 31;
    const int grp  = lane >> 2;
    const int tq   = lane & 3;
    const int wm   = w & 3;
    const int wn   = w >> 2;
    const int row0 = rt * 64, col0 = ct * 64;
    const int tx = tid & 15, ty = tid >> 4;
    const int hidx = ct * 16 + tx;

    const __half* Wg   = (LAYER == 0) ? g_hW0 : g_hW1;
    const float*  bias = (LAYER == 0) ? g_b0  : g_b1;

    // load W tile into smem once
    for (int i = tid; i < 64 * NU4; i += 256) {
        int cc = i / NU4, k = (i % NU4) * 8;
        *(uint4*)&Ws[cc * AST + k] = *(const uint4*)&Wg[(size_t)(col0 + cc) * KTOT + k];
    }
    float4 bv = *(const float4*)&bias[col0 + tx * 4];
    float cst[4] = {0.f, 0.f, 0.f, 0.f};

    unsigned phase = 0;
    __syncthreads();

    for (int e = 0; e <= TT; e++) {
        const bool active = (LAYER == 0) ? (e < TT) : (e >= 1);
        if (active) {
            const int t = (LAYER == 0) ? e : (e - 1);
            const __half* __restrict__ hprev = (LAYER == 0) ? g_h0[t & 1] : g_h1[t & 1];
            // As load: [x | h] or [enc1 | h]
            for (int i = tid; i < 64 * NU4; i += 256) {
                int r = i / NU4, k = (i % NU4) * 8;
                const __half* src;
                if (LAYER == 0)
                    src = (k < 64) ? &g_x[((size_t)(row0 + r) * TT + t) * DD + k]
                                   : &hprev[(row0 + r) * HH + k - 64];
                else
                    src = (k < 256) ? &g_enc1[((size_t)(row0 + r) * TT + t) * HH + k]
                                    : &hprev[(row0 + r) * HH + k - 256];
                *(uint4*)&As[r * AST + k] = *(const uint4*)src;
            }
            __syncthreads();

            // HMMA: warp tile 16x32 via 4 m16n8k16 atoms per k-step
            float acc[4][4];
            #pragma unroll
            for (int j = 0; j < 4; j++)
                #pragma unroll
                for (int i2 = 0; i2 < 4; i2++) acc[j][i2] = 0.f;
            const __half* Ab = As + (wm * 16) * AST;
            const __half* Wb = Ws + (wn * 32) * AST;
            #pragma unroll 4
            for (int ks = 0; ks < KTOT / 16; ks++) {
                const int kb = ks * 16 + 2 * tq;
                uint32_t a0 = *(const uint32_t*)&Ab[(grp    ) * AST + kb    ];
                uint32_t a1 = *(const uint32_t*)&Ab[(grp + 8) * AST + kb    ];
                uint32_t a2 = *(const uint32_t*)&Ab[(grp    ) * AST + kb + 8];
                uint32_t a3 = *(const uint32_t*)&Ab[(grp + 8) * AST + kb + 8];
                #pragma unroll
                for (int j = 0; j < 4; j++) {
                    uint32_t b0 = *(const uint32_t*)&Wb[(j * 8 + grp) * AST + kb    ];
                    uint32_t b1 = *(const uint32_t*)&Wb[(j * 8 + grp) * AST + kb + 8];
                    mma16816(acc[j], a0, a1, a2, a3, b0, b1);
                }
            }
            __syncthreads();   // As reads done; safe to overlay gates

            #pragma unroll
            for (int j = 0; j < 4; j++) {
                int gcol = wn * 32 + j * 8 + 2 * tq;
                int grow = wm * 16 + grp;
                gates[grow * 68 + gcol]           = acc[j][0];
                gates[grow * 68 + gcol + 1]       = acc[j][1];
                gates[(grow + 8) * 68 + gcol]     = acc[j][2];
                gates[(grow + 8) * 68 + gcol + 1] = acc[j][3];
            }
            __syncthreads();

            // fused LSTM epilogue; c-state in registers
            __half* __restrict__ hnew = (LAYER == 0) ? g_h0[(t + 1) & 1] : g_h1[(t + 1) & 1];
            #pragma unroll
            for (int rr = 0; rr < 4; rr++) {
                int rloc = ty * 4 + rr;
                int row  = row0 + rloc;
                float4 g = *(float4*)&gates[rloc * 68 + tx * 4];
                float iv = sigf(g.x + bv.x);
                float fv = sigf(g.y + bv.y);
                float gv = tanhf(g.z + bv.z);
                float ov = sigf(g.w + bv.w);
                float cn = fv * cst[rr] + iv * gv;
                cst[rr] = cn;
                float hv = ov * tanhf(cn);
                __half hh = __float2half(hv);
                hnew[row * HH + hidx] = hh;
                if (LAYER == 0) {
                    g_enc1[((size_t)row * TT + t) * HH + hidx] = hh;
                } else {
                    g_enc[((size_t)row * TT + t) * HH + hidx] = hh;
                    if (t == TT - 1) g_c1[row * HH + hidx] = cn;
                }
            }
        }
        if (e < TT) gridbar(&phase);
    }
}

__global__ __launch_bounds__(256, 1)
void enc_persist_kernel()
{
    int blk = blockIdx.x;
    int sub = blk & 63;
    int ct = sub & 15, rt = sub >> 4;
    if ((blk >> 6) == 0) enc_persist_body<0>(ct, rt);
    else                 enc_persist_body<1>(ct, rt);
}

// ---------------- fused HMMA GEMM + LSTM-cell (decoder cell, R10-proven) -----
__device__ __forceinline__ void lstm_mma_tile(
    const __half* __restrict__ A0, long long lda0, int K0,
    const __half* __restrict__ A1, long long lda1, int K1,
    const __half* __restrict__ W,  int ldw,
    const float* __restrict__ bias,
    float* __restrict__ c, __half* __restrict__ h_out,
    int bx, int by)
{
    extern __shared__ __half sm[];
    __half* As = sm;                   // [2][64][72]
    __half* Ws = sm + 2 * 64 * 72;     // [2][64][72]
    float*  gates = (float*)sm;        // overlay [64][68]

    const int tid  = threadIdx.x;
    const int w    = tid >> 5;
    const int lane = tid & 31;
    const int grp  = lane >> 2;
    const int tq   = lane & 3;
    const int wm   = w & 3;
    const int wn   = w >> 2;
    const int row0 = by * 64, col0 = bx * 64;
    const int nchunks = (K0 + K1) >> 6;
    const int r0l = tid >> 3,         c0l = (tid & 7) * 8;
    const int r1l = (tid + 256) >> 3, c1l = ((tid + 256) & 7) * 8;

    float acc[4][4];
    #pragma unroll
    for (int j = 0; j < 4; j++)
        #pragma unroll
        for (int i = 0; i < 4; i++) acc[j][i] = 0.f;

    uint4 ra0, ra1, rw0, rw1;

    ra0 = *(const uint4*)&A0[(size_t)(row0 + r0l) * lda0 + c0l];
    ra1 = *(const uint4*)&A0[(size_t)(row0 + r1l) * lda0 + c1l];
    rw0 = *(const uint4*)&W [(size_t)(col0 + r0l) * ldw + c0l];
    rw1 = *(const uint4*)&W [(size_t)(col0 + r1l) * ldw + c1l];
    *(uint4*)&As[r0l * 72 + c0l] = ra0;
    *(uint4*)&As[r1l * 72 + c1l] = ra1;
    *(uint4*)&Ws[r0l * 72 + c0l] = rw0;
    *(uint4*)&Ws[r1l * 72 + c1l] = rw1;
    __syncthreads();

    int p = 0;
    for (int ch = 0; ch < nchunks; ch++) {
        const bool more = (ch + 1 < nchunks);
        if (more) {
            const int k0 = (ch + 1) << 6;
            const __half* Aseg; long long ldA; int kk;
            if (k0 < K0) { Aseg = A0; ldA = lda0; kk = k0; }
            else         { Aseg = A1; ldA = lda1; kk = k0 - K0; }
            ra0 = *(const uint4*)&Aseg[(size_t)(row0 + r0l) * ldA + kk + c0l];
            ra1 = *(const uint4*)&Aseg[(size_t)(row0 + r1l) * ldA + kk + c1l];
            rw0 = *(const uint4*)&W[(size_t)(col0 + r0l) * ldw + k0 + c0l];
            rw1 = *(const uint4*)&W[(size_t)(col0 + r1l) * ldw + k0 + c1l];
        }
        const __half* Ab = As + p * 4608 + (wm * 16) * 72;
        const __half* Wb = Ws + p * 4608 + (wn * 32) * 72;
        #pragma unroll
        for (int ks = 0; ks < 4; ks++) {
            const int kb = ks * 16 + 2 * tq;
            uint32_t a0 = *(const uint32_t*)&Ab[(grp    ) * 72 + kb    ];
            uint32_t a1 = *(const uint32_t*)&Ab[(grp + 8) * 72 + kb    ];
            uint32_t a2 = *(const uint32_t*)&Ab[(grp    ) * 72 + kb + 8];
            uint32_t a3 = *(const uint32_t*)&Ab[(grp + 8) * 72 + kb + 8];
            #pragma unroll
            for (int j = 0; j < 4; j++) {
                uint32_t b0 = *(const uint32_t*)&Wb[(j * 8 + grp) * 72 + kb    ];
                uint32_t b1 = *(const uint32_t*)&Wb[(j * 8 + grp) * 72 + kb + 8];
                mma16816(acc[j], a0, a1, a2, a3, b0, b1);
            }
        }
        if (more) {
            const int q = p ^ 1, base = q * 4608;
            *(uint4*)&As[base + r0l * 72 + c0l] = ra0;
            *(uint4*)&As[base + r1l * 72 + c1l] = ra1;
            *(uint4*)&Ws[base + r0l * 72 + c0l] = rw0;
            *(uint4*)&Ws[base + r1l * 72 + c1l] = rw1;
            __syncthreads();
            p = q;
        }
    }

    __syncthreads();
    #pragma unroll
    for (int j = 0; j < 4; j++) {
        int gcol = wn * 32 + j * 8 + 2 * tq;
        int grow = wm * 16 + grp;
        gates[grow * 68 + gcol]           = acc[j][0];
        gates[grow * 68 + gcol + 1]       = acc[j][1];
        gates[(grow + 8) * 68 + gcol]     = acc[j][2];
        gates[(grow + 8) * 68 + gcol + 1] = acc[j][3];
    }
    __syncthreads();

    const int tx = tid & 15, ty = tid >> 4;
    const int hidx = (col0 >> 2) + tx;
    float4 bv = *(const float4*)&bias[col0 + tx * 4];
    #pragma unroll
    for (int rr = 0; rr < 4; rr++) {
        int rloc = ty * 4 + rr;
        int row  = row0 + rloc;
        float4 g = *(float4*)&gates[rloc * 68 + tx * 4];
        float iv = sigf(g.x + bv.x);
        float fv = sigf(g.y + bv.y);
        float gv = tanhf(g.z + bv.z);
        float ov = sigf(g.w + bv.w);
        int ci = row * HH + hidx;
        float cn = fv * c[ci] + iv * gv;
        c[ci] = cn;
        h_out[ci] = __float2half(ov * tanhf(cn));
    }
}

// ---------------- decoder attention (vectorized streamer, 16 warps) ----------
// Lane l owns contiguous cols 8l..8l+7 (one uint4 per enc row). Warp w covers
// timesteps [32w, 32w+32). Online softmax per warp; 16-way combine in smem.
__global__ __launch_bounds__(512)
void dec_attn_kernel(const float* __restrict__ prev_y, long long ldy,
                     const float* __restrict__ Wp, const float* __restrict__ bp, int s)
{
    int b = blockIdx.x;
    __shared__ float sh_h[HH];
    __shared__ float sh_py[DD];
    __shared__ float sh_m[16], sh_s[16];
    __shared__ float sh_part[16][HH];
    int tid = threadIdx.x, lane = tid & 31, w = tid >> 5;

    if (tid < HH) sh_h[tid] = __half2float(g_h1[s & 1][b * HH + tid]);
    else if (tid < HH + DD) sh_py[tid - HH] = prev_y[(long long)b * ldy + (tid - HH)];
    __syncthreads();

    float hreg[8];
    #pragma unroll
    for (int j = 0; j < 8; j++) hreg[j] = sh_h[8 * lane + j];

    float m = -1e30f, ssum = 0.f;
    float accv[8];
    #pragma unroll
    for (int j = 0; j < 8; j++) accv[j] = 0.f;
    const __half* ebase = g_enc + (size_t)b * TT * HH + 8 * lane;

    for (int i = 0; i < 32; i++) {
        int t = w * 32 + i;
        uint4 u = *(const uint4*)&ebase[(size_t)t * HH];
        const __half2* hv = (const __half2*)&u;
        float2 f0 = __half22float2(hv[0]), f1 = __half22float2(hv[1]);
        float2 f2 = __half22float2(hv[2]), f3 = __half22float2(hv[3]);
        float v[8] = { f0.x, f0.y, f1.x, f1.y, f2.x, f2.y, f3.x, f3.y };
        float dot = 0.f;
        #pragma unroll
        for (int j = 0; j < 8; j++) dot = fmaf(v[j], hreg[j], dot);
        #pragma unroll
        for (int o = 16; o > 0; o >>= 1) dot += __shfl_xor_sync(0xffffffffu, dot, o);
        float score = dot * 0.0625f;                 // / sqrt(256)
        float nm  = fmaxf(m, score);
        float esc = __expf(m - nm);
        float pw  = __expf(score - nm);
        ssum = ssum * esc + pw;
        #pragma unroll
        for (int j = 0; j < 8; j++) accv[j] = accv[j] * esc + pw * v[j];
        m = nm;
    }
    if (lane == 0) { sh_m[w] = m; sh_s[w] = ssum; }
    #pragma unroll
    for (int j = 0; j < 8; j++) sh_part[w][8 * lane + j] = accv[j];
    __syncthreads();

    if (tid < HH) {
        float M = sh_m[0];
        #pragma unroll
        for (int ww = 1; ww < 16; ww++) M = fmaxf(M, sh_m[ww]);
        float num = 0.f, den = 0.f;
        #pragma unroll
        for (int ww = 0; ww < 16; ww++) {
            float f = __expf(sh_m[ww] - M);
            den += f * sh_s[ww];
            num += f * sh_part[ww][tid];
        }
        g_inp[b * 512 + 256 + tid] = __float2half(num / den);    // ctx

        float pv = bp[tid];
        #pragma unroll 8
        for (int d = 0; d < DD; d++) pv = fmaf(sh_py[d], Wp[tid * DD + d], pv);
        g_inp[b * 512 + tid] = __float2half(pv);                 // prev_y @ Wp^T + bp
    }
}

// ---------------- decoder LSTM cell ----------------
__global__ __launch_bounds__(256)
void dec_lstm_kernel(int s)
{
    lstm_mma_tile(g_inp, 512, 512,
                  g_h1[s & 1], HH, HH,
                  g_hWd, 768, g_bd,
                  g_c1, g_h1[(s + 1) & 1],
                  blockIdx.x, blockIdx.y);
}

// ---------------- decoder output: y = [h_new | ctx] @ Wo^T + bo --------------
__global__ __launch_bounds__(256)
void dec_y_kernel(float* __restrict__ out, const float* __restrict__ Wo,
                  const float* __restrict__ bo, int s)
{
    __shared__ float sA[16][512];
    int tid = threadIdx.x;
    int rb = blockIdx.x * 16;
    const __half* hN = g_h1[(s + 1) & 1];
    for (int i = tid; i < 16 * 512; i += 256) {
        int r = i >> 9, k = i & 511;
        sA[r][k] = (k < 256) ? __half2float(hN[(rb + r) * HH + k])
                             : __half2float(g_inp[(rb + r) * 512 + k]);
    }
    __syncthreads();
    int j  = tid & 63;
    int r0 = (tid >> 6) * 4;
    float a0 = bo[j], a1 = a0, a2 = a0, a3 = a0;
    const float4* Wrow = reinterpret_cast<const float4*>(Wo + j * 512);
    for (int k4 = 0; k4 < 128; k4++) {
        float4 wv = Wrow[k4];
        int k = k4 * 4;
        a0 = fmaf(wv.x, sA[r0+0][k], a0); a0 = fmaf(wv.y, sA[r0+0][k+1], a0);
        a0 = fmaf(wv.z, sA[r0+0][k+2], a0); a0 = fmaf(wv.w, sA[r0+0][k+3], a0);
        a1 = fmaf(wv.x, sA[r0+1][k], a1); a1 = fmaf(wv.y, sA[r0+1][k+1], a1);
        a1 = fmaf(wv.z, sA[r0+1][k+2], a1); a1 = fmaf(wv.w, sA[r0+1][k+3], a1);
        a2 = fmaf(wv.x, sA[r0+2][k], a2); a2 = fmaf(wv.y, sA[r0+2][k+1], a2);
        a2 = fmaf(wv.z, sA[r0+2][k+2], a2); a2 = fmaf(wv.w, sA[r0+2][k+3], a2);
        a3 = fmaf(wv.x, sA[r0+3][k], a3); a3 = fmaf(wv.y, sA[r0+3][k+1], a3);
        a3 = fmaf(wv.z, sA[r0+3][k+2], a3); a3 = fmaf(wv.w, sA[r0+3][k+3], a3);
    }
    long long base = ((long long)(rb + r0) * WOUT + s) * DD + j;
    out[base]                        = a0;
    out[base + 1LL * WOUT * DD]      = a1;
    out[base + 2LL * WOUT * DD]      = a2;
    out[base + 3LL * WOUT * DD]      = a3;
}

// ---------------- launch ----------------
extern "C" void kernel_launch(void* const* d_in, const int* in_sizes, int n_in,
                              void* d_out, int out_size)
{
    const float* x_in = (const float*)d_in[0];
    int o = (n_in > 1 && in_sizes[1] == 1) ? 2 : 1;
    const float* Wih0 = (const float*)d_in[o + 0];
    const float* Whh0 = (const float*)d_in[o + 1];
    const float* bih0 = (const float*)d_in[o + 2];
    const float* bhh0 = (const float*)d_in[o + 3];
    const float* Wih1 = (const float*)d_in[o + 4];
    const float* Whh1 = (const float*)d_in[o + 5];
    const float* bih1 = (const float*)d_in[o + 6];
    const float* bhh1 = (const float*)d_in[o + 7];
    const float* Wihd = (const float*)d_in[o + 8];
    const float* Whhd = (const float*)d_in[o + 9];
    const float* bihd = (const float*)d_in[o + 10];
    const float* bhhd = (const float*)d_in[o + 11];
    const float* Wp   = (const float*)d_in[o + 12];
    const float* bp   = (const float*)d_in[o + 13];
    const float* Wo   = (const float*)d_in[o + 14];
    const float* bo   = (const float*)d_in[o + 15];
    float* out = (float*)d_out;

    const int smem_enc = 2 * 64 * 520 * 2;        // 133120 B: As + Ws (layer-1 worst case)
    const int smem_dec = (2 * 64 * 72 * 2) * 2;   // 36864 B
    cudaFuncSetAttribute(enc_persist_kernel,
                         cudaFuncAttributeMaxDynamicSharedMemorySize, smem_enc);

    prep_kernel<<<GG, 256>>>(Wih0, Whh0, bih0, bhh0,
                             Wih1, Whh1, bih1, bhh1,
                             Wihd, Whhd, bihd, bhhd);
    xconv_kernel<<<(BB * TT * DD + 255) / 256, 256>>>(x_in);

    // persistent two-layer encoder scan: ONE launch
    enc_persist_kernel<<<128, 256, smem_enc>>>();

    // decoder: 96 steps
    for (int s = 0; s < WOUT; s++) {
        const float* py = (s == 0) ? (x_in + (long long)(TT - 1) * DD)
                                   : (out + (long long)(s - 1) * DD);
        long long ldy = (s == 0) ? (long long)TT * DD : (long long)WOUT * DD;
        dec_attn_kernel<<<BB, 512>>>(py, ldy, Wp, bp, s);
        dec_lstm_kernel<<<dim3(16, 4), 256, smem_dec>>>(s);
        dec_y_kernel<<<16, 256>>>(out, Wo, bo, s);
    }
}

// round 14
// speedup vs baseline: 3.4274x; 1.0237x over previous
#include <cuda_runtime.h>
#include <cuda_fp16.h>
#include <cuda_bf16.h>
#include <cstdint>

// Problem constants
#define DD   64      // input dim
#define HH   256     // hidden dim
#define BB   256     // batch
#define TT   512     // encoder timesteps
#define GG   1024    // 4*H
#define WOUT 96      // decoder steps

// ---------------- static scratch (no cudaMalloc allowed) ----------------
__device__ __half g_hW0[GG * 320];          // fp16 gate-permuted [p][0:64]=Wih0,[64:320]=Whh0
__device__ float  g_b0[GG];
__device__ __half g_hW1[GG * 512];          // [p][0:256]=Wih1, [256:512]=Whh1
__device__ float  g_b1[GG];
__device__ __half g_hWd[GG * 768];          // [p][0:512]=Wih_d, [512:768]=Whh_d
__device__ float  g_bd[GG];
__device__ __half g_x   [(size_t)BB * TT * DD];   // x_in fp16
__device__ __half g_enc1[(size_t)BB * TT * HH];   // layer-0 outputs fp16
__device__ __half g_enc [(size_t)BB * TT * HH];   // layer-1 outputs fp16
__device__ __half g_h0[2][BB * HH];
__device__ __half g_h1[2][BB * HH];
__device__ float  g_c1[BB * HH];
__device__ __half g_inp[BB * 512];          // decoder [p | ctx] fp16

__device__ unsigned g_bar_cnt;
__device__ volatile unsigned g_bar_phase;

// ---------------- prep: gate-interleave + fp16 weights, zero state ----------
// permuted row p = 4k+q  <-  original row q*H + k
__global__ void prep_kernel(
    const float* __restrict__ Wih0, const float* __restrict__ Whh0,
    const float* __restrict__ bih0, const float* __restrict__ bhh0,
    const float* __restrict__ Wih1, const float* __restrict__ Whh1,
    const float* __restrict__ bih1, const float* __restrict__ bhh1,
    const float* __restrict__ Wihd, const float* __restrict__ Whhd,
    const float* __restrict__ bihd, const float* __restrict__ bhhd)
{
    int p = blockIdx.x;          // 0..1023
    int k = p >> 2, q = p & 3;
    int r = q * HH + k;
    int tid = threadIdx.x;       // 256 threads

    if (tid < 64) g_hW0[p * 320 + tid] = __float2half(Wih0[r * 64 + tid]);
    g_hW0[p * 320 +  64 + tid] = __float2half(Whh0[r * 256 + tid]);

    g_hW1[p * 512 +       tid] = __float2half(Wih1[r * 256 + tid]);
    g_hW1[p * 512 + 256 + tid] = __float2half(Whh1[r * 256 + tid]);

    g_hWd[p * 768 +       tid] = __float2half(Wihd[r * 512 + tid]);
    g_hWd[p * 768 + 256 + tid] = __float2half(Wihd[r * 512 + 256 + tid]);
    g_hWd[p * 768 + 512 + tid] = __float2half(Whhd[r * 256 + tid]);

    if (tid == 0) {
        g_b0[p] = bih0[r] + bhh0[r];
        g_b1[p] = bih1[r] + bhh1[r];
        g_bd[p] = bihd[r] + bhhd[r];
        if (p == 0) { g_bar_cnt = 0; g_bar_phase = 0; }
    }
    int idx = p * 256 + tid;     // covers 262144 >= 65536
    if (idx < BB * HH) {
        g_h0[0][idx] = __float2half(0.f); g_h0[1][idx] = __float2half(0.f);
        g_h1[0][idx] = __float2half(0.f); g_h1[1][idx] = __float2half(0.f);
        g_c1[idx] = 0.f;
    }
}

__global__ void xconv_kernel(const float* __restrict__ x)
{
    size_t i = (size_t)blockIdx.x * blockDim.x + threadIdx.x;
    if (i < (size_t)BB * TT * DD) g_x[i] = __float2half(x[i]);
}

__device__ __forceinline__ float sigf(float x) { return 1.f / (1.f + expf(-x)); }

// One HMMA atom: D(16x8) += A(16x16,row) * B(16x8,col), fp16 in, fp32 accum.
__device__ __forceinline__ void mma16816(float* cc,
                                         uint32_t a0, uint32_t a1, uint32_t a2, uint32_t a3,
                                         uint32_t b0, uint32_t b1)
{
    asm volatile(
        "mma.sync.aligned.m16n8k16.row.col.f32.f16.f16.f32 "
        "{%0,%1,%2,%3}, {%4,%5,%6,%7}, {%8,%9}, {%0,%1,%2,%3};"
        : "+f"(cc[0]), "+f"(cc[1]), "+f"(cc[2]), "+f"(cc[3])
        : "r"(a0), "r"(a1), "r"(a2), "r"(a3), "r"(b0), "r"(b1));
}

// ---------------- grid barrier (sense-reversing; fence drops stale L1) -------
__device__ __forceinline__ void gridbar(unsigned* phase)
{
    __syncthreads();
    if (threadIdx.x == 0) {
        unsigned p = *phase;
        __threadfence();                              // publish our writes
        if (atomicAdd(&g_bar_cnt, 1u) == (unsigned)gridDim.x - 1u) {
            atomicExch(&g_bar_cnt, 0u);
            __threadfence();
            g_bar_phase = p + 1u;
        } else {
            while (g_bar_phase == p) { __nanosleep(32); }
        }
        __threadfence();                              // invalidate L1
        *phase = p + 1u;
    }
    __syncthreads();
}

// ---------------- persistent encoder body (one layer, one 64x64 tile) --------
// Weights resident in smem for whole scan; c-state in registers; HMMA core.
template<int LAYER>
__device__ __forceinline__ void enc_persist_body(int ct, int rt)
{
    constexpr int KTOT = (LAYER == 0) ? 320 : 512;
    constexpr int AST  = KTOT + 8;        // smem row stride (halves); bank-safe
    constexpr int NU4  = KTOT / 8;        // uint4 per row

    extern __shared__ __half sm[];
    __half* As    = sm;                   // [64][AST]
    __half* Ws    = sm + 64 * AST;        // [64][AST], persistent
    float*  gates = (float*)sm;           // overlay on As after MMA

    const int tid  = threadIdx.x;
    const int w    = tid >> 5;
    const int lane = tid & 31;
    const int grp  = lane >> 2;
    const int tq   = lane & 3;
    const int wm   = w & 3;
    const int wn   = w >> 2;
    const int row0 = rt * 64, col0 = ct * 64;
    const int tx = tid & 15, ty = tid >> 4;
    const int hidx = ct * 16 + tx;

    const __half* Wg   = (LAYER == 0) ? g_hW0 : g_hW1;
    const float*  bias = (LAYER == 0) ? g_b0  : g_b1;

    // load W tile into smem once
    for (int i = tid; i < 64 * NU4; i += 256) {
        int cc = i / NU4, k = (i % NU4) * 8;
        *(uint4*)&Ws[cc * AST + k] = *(const uint4*)&Wg[(size_t)(col0 + cc) * KTOT + k];
    }
    float4 bv = *(const float4*)&bias[col0 + tx * 4];
    float cst[4] = {0.f, 0.f, 0.f, 0.f};

    unsigned phase = 0;
    __syncthreads();

    for (int e = 0; e <= TT; e++) {
        const bool active = (LAYER == 0) ? (e < TT) : (e >= 1);
        if (active) {
            const int t = (LAYER == 0) ? e : (e - 1);
            const __half* __restrict__ hprev = (LAYER == 0) ? g_h0[t & 1] : g_h1[t & 1];
            // As load: [x | h] or [enc1 | h]
            for (int i = tid; i < 64 * NU4; i += 256) {
                int r = i / NU4, k = (i % NU4) * 8;
                const __half* src;
                if (LAYER == 0)
                    src = (k < 64) ? &g_x[((size_t)(row0 + r) * TT + t) * DD + k]
                                   : &hprev[(row0 + r) * HH + k - 64];
                else
                    src = (k < 256) ? &g_enc1[((size_t)(row0 + r) * TT + t) * HH + k]
                                    : &hprev[(row0 + r) * HH + k - 256];
                *(uint4*)&As[r * AST + k] = *(const uint4*)src;
            }
            __syncthreads();

            // HMMA: warp tile 16x32 via 4 m16n8k16 atoms per k-step
            float acc[4][4];
            #pragma unroll
            for (int j = 0; j < 4; j++)
                #pragma unroll
                for (int i2 = 0; i2 < 4; i2++) acc[j][i2] = 0.f;
            const __half* Ab = As + (wm * 16) * AST;
            const __half* Wb = Ws + (wn * 32) * AST;
            #pragma unroll 4
            for (int ks = 0; ks < KTOT / 16; ks++) {
                const int kb = ks * 16 + 2 * tq;
                uint32_t a0 = *(const uint32_t*)&Ab[(grp    ) * AST + kb    ];
                uint32_t a1 = *(const uint32_t*)&Ab[(grp + 8) * AST + kb    ];
                uint32_t a2 = *(const uint32_t*)&Ab[(grp    ) * AST + kb + 8];
                uint32_t a3 = *(const uint32_t*)&Ab[(grp + 8) * AST + kb + 8];
                #pragma unroll
                for (int j = 0; j < 4; j++) {
                    uint32_t b0 = *(const uint32_t*)&Wb[(j * 8 + grp) * AST + kb    ];
                    uint32_t b1 = *(const uint32_t*)&Wb[(j * 8 + grp) * AST + kb + 8];
                    mma16816(acc[j], a0, a1, a2, a3, b0, b1);
                }
            }
            __syncthreads();   // As reads done; safe to overlay gates

            #pragma unroll
            for (int j = 0; j < 4; j++) {
                int gcol = wn * 32 + j * 8 + 2 * tq;
                int grow = wm * 16 + grp;
                gates[grow * 68 + gcol]           = acc[j][0];
                gates[grow * 68 + gcol + 1]       = acc[j][1];
                gates[(grow + 8) * 68 + gcol]     = acc[j][2];
                gates[(grow + 8) * 68 + gcol + 1] = acc[j][3];
            }
            __syncthreads();

            // fused LSTM epilogue; c-state in registers
            __half* __restrict__ hnew = (LAYER == 0) ? g_h0[(t + 1) & 1] : g_h1[(t + 1) & 1];
            #pragma unroll
            for (int rr = 0; rr < 4; rr++) {
                int rloc = ty * 4 + rr;
                int row  = row0 + rloc;
                float4 g = *(float4*)&gates[rloc * 68 + tx * 4];
                float iv = sigf(g.x + bv.x);
                float fv = sigf(g.y + bv.y);
                float gv = tanhf(g.z + bv.z);
                float ov = sigf(g.w + bv.w);
                float cn = fv * cst[rr] + iv * gv;
                cst[rr] = cn;
                float hv = ov * tanhf(cn);
                __half hh = __float2half(hv);
                hnew[row * HH + hidx] = hh;
                if (LAYER == 0) {
                    g_enc1[((size_t)row * TT + t) * HH + hidx] = hh;
                } else {
                    g_enc[((size_t)row * TT + t) * HH + hidx] = hh;
                    if (t == TT - 1) g_c1[row * HH + hidx] = cn;
                }
            }
        }
        if (e < TT) gridbar(&phase);
    }
}

__global__ __launch_bounds__(256, 1)
void enc_persist_kernel()
{
    int blk = blockIdx.x;
    int sub = blk & 63;
    int ct = sub & 15, rt = sub >> 4;
    if ((blk >> 6) == 0) enc_persist_body<0>(ct, rt);
    else                 enc_persist_body<1>(ct, rt);
}

// ---------------- fused HMMA GEMM + LSTM-cell (decoder cell, R10-proven) -----
__device__ __forceinline__ void lstm_mma_tile(
    const __half* __restrict__ A0, long long lda0, int K0,
    const __half* __restrict__ A1, long long lda1, int K1,
    const __half* __restrict__ W,  int ldw,
    const float* __restrict__ bias,
    float* __restrict__ c, __half* __restrict__ h_out,
    int bx, int by)
{
    extern __shared__ __half sm[];
    __half* As = sm;                   // [2][64][72]
    __half* Ws = sm + 2 * 64 * 72;     // [2][64][72]
    float*  gates = (float*)sm;        // overlay [64][68]

    const int tid  = threadIdx.x;
    const int w    = tid >> 5;
    const int lane = tid & 31;
    const int grp  = lane >> 2;
    const int tq   = lane & 3;
    const int wm   = w & 3;
    const int wn   = w >> 2;
    const int row0 = by * 64, col0 = bx * 64;
    const int nchunks = (K0 + K1) >> 6;
    const int r0l = tid >> 3,         c0l = (tid & 7) * 8;
    const int r1l = (tid + 256) >> 3, c1l = ((tid + 256) & 7) * 8;

    float acc[4][4];
    #pragma unroll
    for (int j = 0; j < 4; j++)
        #pragma unroll
        for (int i = 0; i < 4; i++) acc[j][i] = 0.f;

    uint4 ra0, ra1, rw0, rw1;

    ra0 = *(const uint4*)&A0[(size_t)(row0 + r0l) * lda0 + c0l];
    ra1 = *(const uint4*)&A0[(size_t)(row0 + r1l) * lda0 + c1l];
    rw0 = *(const uint4*)&W [(size_t)(col0 + r0l) * ldw + c0l];
    rw1 = *(const uint4*)&W [(size_t)(col0 + r1l) * ldw + c1l];
    *(uint4*)&As[r0l * 72 + c0l] = ra0;
    *(uint4*)&As[r1l * 72 + c1l] = ra1;
    *(uint4*)&Ws[r0l * 72 + c0l] = rw0;
    *(uint4*)&Ws[r1l * 72 + c1l] = rw1;
    __syncthreads();

    int p = 0;
    for (int ch = 0; ch < nchunks; ch++) {
        const bool more = (ch + 1 < nchunks);
        if (more) {
            const int k0 = (ch + 1) << 6;
            const __half* Aseg; long long ldA; int kk;
            if (k0 < K0) { Aseg = A0; ldA = lda0; kk = k0; }
            else         { Aseg = A1; ldA = lda1; kk = k0 - K0; }
            ra0 = *(const uint4*)&Aseg[(size_t)(row0 + r0l) * ldA + kk + c0l];
            ra1 = *(const uint4*)&Aseg[(size_t)(row0 + r1l) * ldA + kk + c1l];
            rw0 = *(const uint4*)&W[(size_t)(col0 + r0l) * ldw + k0 + c0l];
            rw1 = *(const uint4*)&W[(size_t)(col0 + r1l) * ldw + k0 + c1l];
        }
        const __half* Ab = As + p * 4608 + (wm * 16) * 72;
        const __half* Wb = Ws + p * 4608 + (wn * 32) * 72;
        #pragma unroll
        for (int ks = 0; ks < 4; ks++) {
            const int kb = ks * 16 + 2 * tq;
            uint32_t a0 = *(const uint32_t*)&Ab[(grp    ) * 72 + kb    ];
            uint32_t a1 = *(const uint32_t*)&Ab[(grp + 8) * 72 + kb    ];
            uint32_t a2 = *(const uint32_t*)&Ab[(grp    ) * 72 + kb + 8];
            uint32_t a3 = *(const uint32_t*)&Ab[(grp + 8) * 72 + kb + 8];
            #pragma unroll
            for (int j = 0; j < 4; j++) {
                uint32_t b0 = *(const uint32_t*)&Wb[(j * 8 + grp) * 72 + kb    ];
                uint32_t b1 = *(const uint32_t*)&Wb[(j * 8 + grp) * 72 + kb + 8];
                mma16816(acc[j], a0, a1, a2, a3, b0, b1);
            }
        }
        if (more) {
            const int q = p ^ 1, base = q * 4608;
            *(uint4*)&As[base + r0l * 72 + c0l] = ra0;
            *(uint4*)&As[base + r1l * 72 + c1l] = ra1;
            *(uint4*)&Ws[base + r0l * 72 + c0l] = rw0;
            *(uint4*)&Ws[base + r1l * 72 + c1l] = rw1;
            __syncthreads();
            p = q;
        }
    }

    __syncthreads();
    #pragma unroll
    for (int j = 0; j < 4; j++) {
        int gcol = wn * 32 + j * 8 + 2 * tq;
        int grow = wm * 16 + grp;
        gates[grow * 68 + gcol]           = acc[j][0];
        gates[grow * 68 + gcol + 1]       = acc[j][1];
        gates[(grow + 8) * 68 + gcol]     = acc[j][2];
        gates[(grow + 8) * 68 + gcol + 1] = acc[j][3];
    }
    __syncthreads();

    const int tx = tid & 15, ty = tid >> 4;
    const int hidx = (col0 >> 2) + tx;
    float4 bv = *(const float4*)&bias[col0 + tx * 4];
    #pragma unroll
    for (int rr = 0; rr < 4; rr++) {
        int rloc = ty * 4 + rr;
        int row  = row0 + rloc;
        float4 g = *(float4*)&gates[rloc * 68 + tx * 4];
        float iv = sigf(g.x + bv.x);
        float fv = sigf(g.y + bv.y);
        float gv = tanhf(g.z + bv.z);
        float ov = sigf(g.w + bv.w);
        int ci = row * HH + hidx;
        float cn = fv * c[ci] + iv * gv;
        c[ci] = cn;
        h_out[ci] = __float2half(ov * tanhf(cn));
    }
}

// ---------------- decoder attention (plain-softmax streamer, 16 warps) -------
// Scores bounded: |h|<=1, |enc|<=1 => |dot|<=256, score=dot/16 in [-16,16],
// exp(score) <= 8.9e6, 512-term sum < 5e9: safe in fp32 without max shift.
// Iterations independent -> loads batched, shuffle trees overlap.
__global__ __launch_bounds__(512)
void dec_attn_kernel(const float* __restrict__ prev_y, long long ldy,
                     const float* __restrict__ Wp, const float* __restrict__ bp, int s)
{
    int b = blockIdx.x;
    __shared__ float sh_h[HH];
    __shared__ float sh_py[DD];
    __shared__ float sh_s[16];
    __shared__ float sh_part[16][HH];
    int tid = threadIdx.x, lane = tid & 31, w = tid >> 5;

    if (tid < HH) sh_h[tid] = __half2float(g_h1[s & 1][b * HH + tid]);
    else if (tid < HH + DD) sh_py[tid - HH] = prev_y[(long long)b * ldy + (tid - HH)];
    __syncthreads();

    float hreg[8];
    #pragma unroll
    for (int j = 0; j < 8; j++) hreg[j] = sh_h[8 * lane + j];

    float ssum = 0.f;
    float accv[8];
    #pragma unroll
    for (int j = 0; j < 8; j++) accv[j] = 0.f;
    const __half* ebase = g_enc + (size_t)b * TT * HH + 8 * lane;

    #pragma unroll 4
    for (int i = 0; i < 32; i++) {
        int t = w * 32 + i;
        uint4 u = *(const uint4*)&ebase[(size_t)t * HH];
        const __half2* hv = (const __half2*)&u;
        float2 f0 = __half22float2(hv[0]), f1 = __half22float2(hv[1]);
        float2 f2 = __half22float2(hv[2]), f3 = __half22float2(hv[3]);
        float v[8] = { f0.x, f0.y, f1.x, f1.y, f2.x, f2.y, f3.x, f3.y };
        float dot = 0.f;
        #pragma unroll
        for (int j = 0; j < 8; j++) dot = fmaf(v[j], hreg[j], dot);
        #pragma unroll
        for (int o = 16; o > 0; o >>= 1) dot += __shfl_xor_sync(0xffffffffu, dot, o);
        float pw = __expf(dot * 0.0625f);            // exp(score), no max shift
        ssum += pw;
        #pragma unroll
        for (int j = 0; j < 8; j++) accv[j] = fmaf(pw, v[j], accv[j]);
    }
    if (lane == 0) sh_s[w] = ssum;
    #pragma unroll
    for (int j = 0; j < 8; j++) sh_part[w][8 * lane + j] = accv[j];
    __syncthreads();

    if (tid < HH) {
        float num = 0.f, den = 0.f;
        #pragma unroll
        for (int ww = 0; ww < 16; ww++) {
            den += sh_s[ww];
            num += sh_part[ww][tid];
        }
        g_inp[b * 512 + 256 + tid] = __float2half(num / den);    // ctx

        float pv = bp[tid];
        #pragma unroll 8
        for (int d = 0; d < DD; d++) pv = fmaf(sh_py[d], Wp[tid * DD + d], pv);
        g_inp[b * 512 + tid] = __float2half(pv);                 // prev_y @ Wp^T + bp
    }
}

// ---------------- decoder LSTM cell ----------------
__global__ __launch_bounds__(256)
void dec_lstm_kernel(int s)
{
    lstm_mma_tile(g_inp, 512, 512,
                  g_h1[s & 1], HH, HH,
                  g_hWd, 768, g_bd,
                  g_c1, g_h1[(s + 1) & 1],
                  blockIdx.x, blockIdx.y);
}

// ---------------- decoder output: y = [h_new | ctx] @ Wo^T + bo --------------
__global__ __launch_bounds__(256)
void dec_y_kernel(float* __restrict__ out, const float* __restrict__ Wo,
                  const float* __restrict__ bo, int s)
{
    __shared__ float sA[16][512];
    int tid = threadIdx.x;
    int rb = blockIdx.x * 16;
    const __half* hN = g_h1[(s + 1) & 1];
    for (int i = tid; i < 16 * 512; i += 256) {
        int r = i >> 9, k = i & 511;
        sA[r][k] = (k < 256) ? __half2float(hN[(rb + r) * HH + k])
                             : __half2float(g_inp[(rb + r) * 512 + k]);
    }
    __syncthreads();
    int j  = tid & 63;
    int r0 = (tid >> 6) * 4;
    float a0 = bo[j], a1 = a0, a2 = a0, a3 = a0;
    const float4* Wrow = reinterpret_cast<const float4*>(Wo + j * 512);
    for (int k4 = 0; k4 < 128; k4++) {
        float4 wv = Wrow[k4];
        int k = k4 * 4;
        a0 = fmaf(wv.x, sA[r0+0][k], a0); a0 = fmaf(wv.y, sA[r0+0][k+1], a0);
        a0 = fmaf(wv.z, sA[r0+0][k+2], a0); a0 = fmaf(wv.w, sA[r0+0][k+3], a0);
        a1 = fmaf(wv.x, sA[r0+1][k], a1); a1 = fmaf(wv.y, sA[r0+1][k+1], a1);
        a1 = fmaf(wv.z, sA[r0+1][k+2], a1); a1 = fmaf(wv.w, sA[r0+1][k+3], a1);
        a2 = fmaf(wv.x, sA[r0+2][k], a2); a2 = fmaf(wv.y, sA[r0+2][k+1], a2);
        a2 = fmaf(wv.z, sA[r0+2][k+2], a2); a2 = fmaf(wv.w, sA[r0+2][k+3], a2);
        a3 = fmaf(wv.x, sA[r0+3][k], a3); a3 = fmaf(wv.y, sA[r0+3][k+1], a3);
        a3 = fmaf(wv.z, sA[r0+3][k+2], a3); a3 = fmaf(wv.w, sA[r0+3][k+3], a3);
    }
    long long base = ((long long)(rb + r0) * WOUT + s) * DD + j;
    out[base]                        = a0;
    out[base + 1LL * WOUT * DD]      = a1;
    out[base + 2LL * WOUT * DD]      = a2;
    out[base + 3LL * WOUT * DD]      = a3;
}

// ---------------- launch ----------------
extern "C" void kernel_launch(void* const* d_in, const int* in_sizes, int n_in,
                              void* d_out, int out_size)
{
    const float* x_in = (const float*)d_in[0];
    int o = (n_in > 1 && in_sizes[1] == 1) ? 2 : 1;
    const float* Wih0 = (const float*)d_in[o + 0];
    const float* Whh0 = (const float*)d_in[o + 1];
    const float* bih0 = (const float*)d_in[o + 2];
    const float* bhh0 = (const float*)d_in[o + 3];
    const float* Wih1 = (const float*)d_in[o + 4];
    const float* Whh1 = (const float*)d_in[o + 5];
    const float* bih1 = (const float*)d_in[o + 6];
    const float* bhh1 = (const float*)d_in[o + 7];
    const float* Wihd = (const float*)d_in[o + 8];
    const float* Whhd = (const float*)d_in[o + 9];
    const float* bihd = (const float*)d_in[o + 10];
    const float* bhhd = (const float*)d_in[o + 11];
    const float* Wp   = (const float*)d_in[o + 12];
    const float* bp   = (const float*)d_in[o + 13];
    const float* Wo   = (const float*)d_in[o + 14];
    const float* bo   = (const float*)d_in[o + 15];
    float* out = (float*)d_out;

    const int smem_enc = 2 * 64 * 520 * 2;        // 133120 B: As + Ws (layer-1 worst case)
    const int smem_dec = (2 * 64 * 72 * 2) * 2;   // 36864 B
    cudaFuncSetAttribute(enc_persist_kernel,
                         cudaFuncAttributeMaxDynamicSharedMemorySize, smem_enc);

    prep_kernel<<<GG, 256>>>(Wih0, Whh0, bih0, bhh0,
                             Wih1, Whh1, bih1, bhh1,
                             Wihd, Whhd, bihd, bhhd);
    xconv_kernel<<<(BB * TT * DD + 255) / 256, 256>>>(x_in);

    // persistent two-layer encoder scan: ONE launch
    enc_persist_kernel<<<128, 256, smem_enc>>>();

    // decoder: 96 steps
    for (int s = 0; s < WOUT; s++) {
        const float* py = (s == 0) ? (x_in + (long long)(TT - 1) * DD)
                                   : (out + (long long)(s - 1) * DD);
        long long ldy = (s == 0) ? (long long)TT * DD : (long long)WOUT * DD;
        dec_attn_kernel<<<BB, 512>>>(py, ldy, Wp, bp, s);
        dec_lstm_kernel<<<dim3(16, 4), 256, smem_dec>>>(s);
        dec_y_kernel<<<16, 256>>>(out, Wo, bo, s);
    }
}